// round 15
// baseline (speedup 1.0000x reference)
#include <cuda_runtime.h>
#include <cuda_bf16.h>
#include <math.h>
#include <stdint.h>

// Problem dims (fixed)
#define Bz   2
#define Sq   2048
#define Dm   2048
#define Hh   16
#define DHd  128
#define DFFd 8192
#define ROWS (Bz*Sq)       // 4096
#define BHn  (Bz*Hh)       // 32
#define EPSn 1e-6f

// ================= PTX helpers =================
__device__ __forceinline__ uint32_t smem_u32(const void* p){
    uint32_t r;
    asm("{ .reg .u64 t; cvta.to.shared.u64 t, %1; cvt.u32.u64 %0, t; }" : "=r"(r) : "l"(p));
    return r;
}
#define MB_INIT(addr,cnt) asm volatile("mbarrier.init.shared.b64 [%0], %1;"::"r"(addr),"r"(cnt):"memory")
#define MB_EXPECT_TX(addr,tx) asm volatile("mbarrier.arrive.expect_tx.shared.b64 _, [%0], %1;"::"r"(addr),"r"(tx):"memory")
#define MB_ARRIVE(addr) asm volatile("mbarrier.arrive.shared.b64 _, [%0];"::"r"(addr):"memory")
#define MB_WAIT(addr, ph) do { \
    asm volatile("{\n\t.reg .pred P1;\n\tWL%=:\n\t" \
        "mbarrier.try_wait.parity.acquire.cta.shared::cta.b64 P1, [%0], %1, 0x989680;\n\t" \
        "@P1 bra.uni WD%=;\n\tbra.uni WL%=;\n\tWD%=:\n\t}" \
        :: "r"(addr), "r"(ph) : "memory"); } while(0)
#define BULK16K(dst, src, mb) asm volatile( \
    "cp.async.bulk.shared::cta.global.mbarrier::complete_tx::bytes [%0], [%1], %2, [%3];" \
    :: "r"(dst), "l"(src), "r"(16384), "r"(mb) : "memory")
#define LDSM4(r0,r1,r2,r3,addr) asm volatile( \
    "ldmatrix.sync.aligned.m8n8.x4.shared.b16 {%0,%1,%2,%3},[%4];" \
    : "=r"(r0),"=r"(r1),"=r"(r2),"=r"(r3) : "r"(addr))
#define MMA16816(c, a, b0, b1) asm volatile( \
    "mma.sync.aligned.m16n8k16.row.col.f32.bf16.bf16.f32 " \
    "{%0,%1,%2,%3},{%4,%5,%6,%7},{%8,%9},{%0,%1,%2,%3};" \
    : "+f"((c)[0]),"+f"((c)[1]),"+f"((c)[2]),"+f"((c)[3]) \
    : "r"((a)[0]),"r"((a)[1]),"r"((a)[2]),"r"((a)[3]), "r"(b0),"r"(b1))
#define SWZ(o) ((o) ^ (((o)>>3)&0x70))

// fast exact-enough gelu: Abramowitz-Stegun 7.1.26 erf (|abs err|<=1.5e-7)
__device__ __forceinline__ float gelu_fast(float x){
    float z = fabsf(x) * 0.7071067811865475f;
    float t = __fdividef(1.f, fmaf(0.3275911f, z, 1.f));
    float p = fmaf(1.061405429f, t, -1.453152027f);
    p = fmaf(p, t, 1.421413741f);
    p = fmaf(p, t, -0.284496736f);
    p = fmaf(p, t, 0.254829592f);
    float e = p * t * __expf(-z*z);
    float er = 1.f - e;
    er = (x < 0.f) ? -er : er;
    return 0.5f * x * (1.f + er);
}

// ================= scratch (device globals) =================
__device__ float g_u   [(size_t)ROWS*Dm];
__device__ float g_ax  [(size_t)BHn*Sq];        // -gsc*x0_q
__device__ float g_bx  [(size_t)BHn*Sq];        // x0_k

// bf16 hi/lo tiled-swizzled (TS) operands, uint4 granules (= elems/8).
__device__ uint4 g_vh  [(size_t)ROWS*Dm/8],   g_vl  [(size_t)ROWS*Dm/8];
__device__ uint4 g_ath [(size_t)ROWS*Dm/8],   g_atl [(size_t)ROWS*Dm/8];
__device__ uint4 g_fh  [(size_t)ROWS*DFFd/8], g_fl  [(size_t)ROWS*DFFd/8];
__device__ uint4 g_qh  [(size_t)BHn*Sq*DHd/8], g_ql [(size_t)BHn*Sq*DHd/8];
__device__ uint4 g_kh  [(size_t)BHn*Sq*DHd/8], g_klo[(size_t)BHn*Sq*DHd/8];
__device__ uint4 g_vth [(size_t)BHn*DHd*Sq/8], g_vtl[(size_t)BHn*DHd*Sq/8];
__device__ uint4 g_WqTh[(size_t)Dm*Dm/8], g_WqTl[(size_t)Dm*Dm/8];
__device__ uint4 g_WkTh[(size_t)Dm*Dm/8], g_WkTl[(size_t)Dm*Dm/8];
__device__ uint4 g_WvTh[(size_t)Dm*Dm/8], g_WvTl[(size_t)Dm*Dm/8];
__device__ uint4 g_WoTh[(size_t)Dm*Dm/8], g_WoTl[(size_t)Dm*Dm/8];
__device__ uint4 g_W1Th[(size_t)Dm*DFFd/8], g_W1Tl[(size_t)Dm*DFFd/8];
__device__ uint4 g_W2Th[(size_t)Dm*DFFd/8], g_W2Tl[(size_t)Dm*DFFd/8];

union Pack8 { __nv_bfloat16 b[8]; uint4 v; };

// ================= reductions =================
__device__ __forceinline__ float warpSum(float v){
    #pragma unroll
    for (int o=16;o;o>>=1) v += __shfl_xor_sync(0xffffffffu, v, o);
    return v;
}
__device__ __forceinline__ float blockSum(float v){
    __shared__ float sh[32];
    int lane = threadIdx.x & 31, w = threadIdx.x >> 5, nw = (blockDim.x + 31) >> 5;
    v = warpSum(v);
    __syncthreads();
    if (lane == 0) sh[w] = v;
    __syncthreads();
    float r = (lane < nw) ? sh[lane] : 0.f;
    return warpSum(r);
}

__device__ __forceinline__ void split_pack(const float* xs, Pack8& H, Pack8& L){
    #pragma unroll
    for (int j=0;j<8;j++){
        __nv_bfloat16 h = __float2bfloat16(xs[j]);
        H.b[j] = h;
        L.b[j] = __float2bfloat16(xs[j] - __bfloat162float(h));
    }
}

// ================= fused elementwise kernels =================
// NOTE: x rows have stride 2049 floats (+1 offset) -> NOT 16B aligned; load scalars.
__global__ void k_lognorm1(const float* __restrict__ x, const float* __restrict__ scale,
                           float* __restrict__ u, uint4* __restrict__ vh, uint4* __restrict__ vl){
    int row = blockIdx.x, t = threadIdx.x;
    const float* xr = x + (size_t)row*(Dm+1) + 1 + t*8;
    float xs[8];
    #pragma unroll
    for (int j=0;j<8;j++) xs[j] = xr[j];
    float ss = 0.f;
    #pragma unroll
    for (int j=0;j<8;j++) ss += xs[j]*xs[j];
    float n2 = blockSum(ss);
    float a  = sqrtf(n2);
    float f  = (a < 1e-6f) ? (1.f - a*a*(1.f/6.f)) : (asinhf(a)/fmaxf(a,1e-12f));
    float rms = sqrtf(f*f*n2*(1.f/(float)Dm) + EPSn);
    float inv = 1.f/rms;
    float4 S0 = *(const float4*)(scale + t*8), S1 = *(const float4*)(scale + t*8 + 4);
    float sc[8] = {S0.x,S0.y,S0.z,S0.w,S1.x,S1.y,S1.z,S1.w};
    float us[8], vs[8];
    #pragma unroll
    for (int j=0;j<8;j++){ us[j] = f*xs[j]; vs[j] = sc[j]*us[j]*inv; }
    float* ur = u + (size_t)row*Dm + t*8;
    *(float4*)ur     = make_float4(us[0],us[1],us[2],us[3]);
    *(float4*)(ur+4) = make_float4(us[4],us[5],us[6],us[7]);
    Pack8 H, L; split_pack(vs, H, L);
    uint32_t tr = row>>7, rl = row&127;
    int kc = t>>3, gg = t&7;
    size_t blk = (((size_t)tr*(Dm/64) + kc)<<10) + (SWZ((uint32_t)(rl*128 + gg*16))>>4);
    vh[blk] = H.v; vl[blk] = L.v;
}

__global__ void k_norm2(const float* __restrict__ u, const float* __restrict__ scale,
                        uint4* __restrict__ vh, uint4* __restrict__ vl){
    int row = blockIdx.x, t = threadIdx.x;
    const float* ur = u + (size_t)row*Dm + t*8;
    float4 A = *(const float4*)ur, B = *(const float4*)(ur+4);
    float xs[8] = {A.x,A.y,A.z,A.w,B.x,B.y,B.z,B.w};
    float ss = 0.f;
    #pragma unroll
    for (int j=0;j<8;j++) ss += xs[j]*xs[j];
    float n2 = blockSum(ss);
    float rms = sqrtf(n2*(1.f/(float)Dm) + EPSn);
    float inv = 1.f/rms;
    float4 S0 = *(const float4*)(scale + t*8), S1 = *(const float4*)(scale + t*8 + 4);
    float sc[8] = {S0.x,S0.y,S0.z,S0.w,S1.x,S1.y,S1.z,S1.w};
    float vs[8];
    #pragma unroll
    for (int j=0;j<8;j++) vs[j] = sc[j]*xs[j]*inv;
    Pack8 H, L; split_pack(vs, H, L);
    uint32_t tr = row>>7, rl = row&127;
    int kc = t>>3, gg = t&7;
    size_t blk = (((size_t)tr*(Dm/64) + kc)<<10) + (SWZ((uint32_t)(rl*128 + gg*16))>>4);
    vh[blk] = H.v; vl[blk] = L.v;
}

__global__ void k_expmap(const float* __restrict__ u, float* __restrict__ out){
    int row = blockIdx.x, tid = threadIdx.x;
    const float* ur = u + (size_t)row*Dm;
    float loc[8]; float s = 0.f;
    #pragma unroll
    for (int j=0;j<8;j++){ float t = ur[tid + j*256]; loc[j]=t; s += t*t; }
    float n2 = blockSum(s);
    float a = sqrtf(n2);
    float sinc = (a < 1e-6f) ? (1.f + a*a*(1.f/6.f)) : (sinhf(a)/fmaxf(a,1e-12f));
    float x0 = sqrtf(1.f + sinc*sinc*n2);
    float* o = out + (size_t)row*(Dm+1);
    if (tid==0) o[0] = x0;
    #pragma unroll
    for (int j=0;j<8;j++){ int d = tid + j*256; o[1+d] = sinc*loc[j]; }
}

// ================= weight split =================
__global__ void k_split_wT(const float* __restrict__ W, uint4* __restrict__ Hi,
                           uint4* __restrict__ Lo, int K, int N, int ld){
    __shared__ float s[64][129];
    int tr = blockIdx.x, kc = blockIdx.y;
    int ntc = K >> 6;
    int n0 = tr*128, k0 = kc*64;
    int col = threadIdx.x & 127, r0 = threadIdx.x >> 7;
    #pragma unroll
    for (int i=0;i<32;i++){
        int r = r0 + i*2;
        s[r][col] = W[(size_t)(k0+r)*ld + n0 + col];
    }
    __syncthreads();
    size_t blk = ((size_t)tr*ntc + kc)*1024;
    #pragma unroll
    for (int i=0;i<4;i++){
        int gid = threadIdx.x + i*256;
        int nl = gid >> 3, g = gid & 7;
        Pack8 uh, ul;
        #pragma unroll
        for (int j=0;j<8;j++){
            float x = s[g*8+j][nl];
            __nv_bfloat16 h = __float2bfloat16(x);
            uh.b[j] = h;
            ul.b[j] = __float2bfloat16(x - __bfloat162float(h));
        }
        uint32_t off = SWZ((uint32_t)(nl*128 + g*16)) >> 4;
        Hi[blk + off] = uh.v;
        Lo[blk + off] = ul.v;
    }
}

// ================= HMMA bf16x3 pipelined GEMM: 256(M) x 128(N) tile, 512 thr =================
// Mainloop uses software-pipelined A fragments (double-buffered; prefetch mt+1
// before mt's MMAs) so LDSM latency hides under MMA issue. Arithmetic order
// per accumulator unchanged.
// EPI: 0 fp32 out; 2 fp32 += ADD; 3 TS out; 4 gelu + TS out; 6 Q-lorentz TS+ax;
//      7 K-lorentz TS+bx; 8 V-transpose TS.
#define STAGE_B 98304
#define HM_SMEM (2*STAGE_B + 1024)
#define GSCq 0.1767766952966369f

template<int EPI>
__global__ void __launch_bounds__(512, 1)
hmma_gemm(const uint4* __restrict__ Ah, const uint4* __restrict__ Al,
          const uint4* __restrict__ Bh, const uint4* __restrict__ Bl,
          float* __restrict__ C, const float* __restrict__ ADD,
          uint4* __restrict__ OHi, uint4* __restrict__ OLo,
          float* __restrict__ AXout, const float* __restrict__ HK,
          int nk, int ldc, int ntc, int mtb, int ntb, long long sC){
    extern __shared__ char dsm[];
    __shared__ __align__(8) unsigned long long s_mbar[4];
    __shared__ float s_red[256][4];
    int tnx = blockIdx.x, tmy = blockIdx.y, bz = blockIdx.z;
    int nkc = nk;
    int atr0 = bz*mtb + 2*tmy;
    int btr  = bz*ntb + tnx;

    uint32_t ab = (smem_u32(dsm) + 1023) & ~1023u;
    int tid = threadIdx.x, wid = tid >> 5, l = tid & 31;
    int wm = wid >> 2, wn = wid & 3;

    uint32_t mb[2], me[2];
    if (tid == 0){
        MB_INIT(smem_u32(&s_mbar[0]), 1);
        MB_INIT(smem_u32(&s_mbar[1]), 1);
        MB_INIT(smem_u32(&s_mbar[2]), 16);
        MB_INIT(smem_u32(&s_mbar[3]), 16);
    }
    mb[0] = smem_u32(&s_mbar[0]); mb[1] = smem_u32(&s_mbar[1]);
    me[0] = smem_u32(&s_mbar[2]); me[1] = smem_u32(&s_mbar[3]);
    __syncthreads();

    if (tid == 0){
        int pre = min(2, nkc);
        for (int c = 0; c < pre; c++){
            uint32_t base = ab + c*STAGE_B;
            MB_EXPECT_TX(mb[c], STAGE_B);
            BULK16K(base,         (const void*)(Ah + ((size_t)atr0*nk + c)*1024), mb[c]);
            BULK16K(base + 16384, (const void*)(Ah + ((size_t)(atr0+1)*nk + c)*1024), mb[c]);
            BULK16K(base + 32768, (const void*)(Al + ((size_t)atr0*nk + c)*1024), mb[c]);
            BULK16K(base + 49152, (const void*)(Al + ((size_t)(atr0+1)*nk + c)*1024), mb[c]);
            BULK16K(base + 65536, (const void*)(Bh + ((size_t)btr*nk + c)*1024), mb[c]);
            BULK16K(base + 81920, (const void*)(Bl + ((size_t)btr*nk + c)*1024), mb[c]);
        }
    }

    int arow[4], brow[2];
    #pragma unroll
    for (int mt=0; mt<4; mt++)
        arow[mt] = ((wm&1)*64 + mt*16 + (l&7) + ((l>>3)&1)*8) * 128;
    #pragma unroll
    for (int p=0; p<2; p++)
        brow[p] = (wn*32 + p*16 + ((l>>4)&1)*8 + (l&7)) * 128;
    int akg = (l>>4)&1, bkg = (l>>3)&1, l7 = l&7;
    uint32_t ablk = (uint32_t)(wm>>1)*16384u;

    float acc[4][4][4];
    #pragma unroll
    for (int i=0;i<4;i++)
        #pragma unroll
        for (int j=0;j<4;j++)
            #pragma unroll
            for (int t=0;t<4;t++) acc[i][j][t] = 0.f;

    for (int c = 0; c < nkc; c++){
        int s = c & 1;
        int ph = (c>>1)&1;
        MB_WAIT(mb[s], ph);
        uint32_t stg = ab + s*STAGE_B;
        uint32_t aHb = stg + ablk;
        uint32_t aLb = aHb + 32768;
        uint32_t bHb = stg + 65536, bLb = stg + 81920;
        #pragma unroll
        for (int kk = 0; kk < 4; kk++){
            int kxA = ((kk*2 + akg) ^ l7) << 4;
            int kxB = ((kk*2 + bkg) ^ l7) << 4;
            uint32_t bhr[4][2], blr[4][2];
            #pragma unroll
            for (int p=0; p<2; p++){
                LDSM4(bhr[2*p][0],bhr[2*p][1],bhr[2*p+1][0],bhr[2*p+1][1], bHb + brow[p] + kxB);
                LDSM4(blr[2*p][0],blr[2*p][1],blr[2*p+1][0],blr[2*p+1][1], bLb + brow[p] + kxB);
            }
            // software-pipelined A fragments (double buffer)
            uint32_t ah2[2][4], al2[2][4];
            LDSM4(ah2[0][0],ah2[0][1],ah2[0][2],ah2[0][3], aHb + arow[0] + kxA);
            LDSM4(al2[0][0],al2[0][1],al2[0][2],al2[0][3], aLb + arow[0] + kxA);
            #pragma unroll
            for (int mt=0; mt<4; mt++){
                const int cur = mt & 1, nxt = cur ^ 1;
                if (mt < 3){
                    LDSM4(ah2[nxt][0],ah2[nxt][1],ah2[nxt][2],ah2[nxt][3], aHb + arow[mt+1] + kxA);
                    LDSM4(al2[nxt][0],al2[nxt][1],al2[nxt][2],al2[nxt][3], aLb + arow[mt+1] + kxA);
                }
                #pragma unroll
                for (int nt=0; nt<4; nt++)
                    MMA16816(acc[mt][nt], ah2[cur], bhr[nt][0], bhr[nt][1]);
                #pragma unroll
                for (int nt=0; nt<4; nt++)
                    MMA16816(acc[mt][nt], ah2[cur], blr[nt][0], blr[nt][1]);
                #pragma unroll
                for (int nt=0; nt<4; nt++)
                    MMA16816(acc[mt][nt], al2[cur], bhr[nt][0], bhr[nt][1]);
            }
        }
        if (l == 0) MB_ARRIVE(me[s]);
        if (tid == 0 && c + 2 < nkc){
            MB_WAIT(me[s], ph);
            int cc = c + 2;
            uint32_t base = ab + s*STAGE_B;
            MB_EXPECT_TX(mb[s], STAGE_B);
            BULK16K(base,         (const void*)(Ah + ((size_t)atr0*nk + cc)*1024), mb[s]);
            BULK16K(base + 16384, (const void*)(Ah + ((size_t)(atr0+1)*nk + cc)*1024), mb[s]);
            BULK16K(base + 32768, (const void*)(Al + ((size_t)atr0*nk + cc)*1024), mb[s]);
            BULK16K(base + 49152, (const void*)(Al + ((size_t)(atr0+1)*nk + cc)*1024), mb[s]);
            BULK16K(base + 65536, (const void*)(Bh + ((size_t)btr*nk + cc)*1024), mb[s]);
            BULK16K(base + 81920, (const void*)(Bl + ((size_t)btr*nk + cc)*1024), mb[s]);
        }
    }

    // -------- epilogue --------
    if (EPI == 3 || EPI == 4){
        int otrBase = tmy*2, ocol0 = tnx*128;
        int otr = otrBase + (wm>>1);
        char* HiB = (char*)OHi;
        char* LoB = (char*)OLo;
        #pragma unroll
        for (int mt=0; mt<4; mt++){
            int rl = (wm&1)*64 + mt*16 + (l>>2);
            uint32_t ro0 = (uint32_t)(rl*128), ro1 = (uint32_t)((rl+8)*128);
            #pragma unroll
            for (int nt=0; nt<4; nt++){
                int col = ocol0 + wn*32 + nt*8 + (l&3)*2;
                float v0 = acc[mt][nt][0], v1 = acc[mt][nt][1];
                float v2 = acc[mt][nt][2], v3 = acc[mt][nt][3];
                if (EPI == 4){
                    v0 = gelu_fast(v0); v1 = gelu_fast(v1);
                    v2 = gelu_fast(v2); v3 = gelu_fast(v3);
                }
                int kcn = col>>6, g = (col>>3)&7, w2 = (col&7)*2;
                size_t blkB = (((size_t)otr*ntc + kcn)<<14);
                uint32_t o0 = SWZ(ro0 + g*16) + w2;
                uint32_t o1 = SWZ(ro1 + g*16) + w2;
                __nv_bfloat16 h0 = __float2bfloat16(v0), h1 = __float2bfloat16(v1);
                __nv_bfloat16 h2 = __float2bfloat16(v2), h3 = __float2bfloat16(v3);
                __nv_bfloat16 l0 = __float2bfloat16(v0 - __bfloat162float(h0));
                __nv_bfloat16 l1 = __float2bfloat16(v1 - __bfloat162float(h1));
                __nv_bfloat16 l2 = __float2bfloat16(v2 - __bfloat162float(h2));
                __nv_bfloat16 l3 = __float2bfloat16(v3 - __bfloat162float(h3));
                *(uint32_t*)(HiB + blkB + o0) = (uint32_t)__bfloat16_as_ushort(h0) | ((uint32_t)__bfloat16_as_ushort(h1)<<16);
                *(uint32_t*)(LoB + blkB + o0) = (uint32_t)__bfloat16_as_ushort(l0) | ((uint32_t)__bfloat16_as_ushort(l1)<<16);
                *(uint32_t*)(HiB + blkB + o1) = (uint32_t)__bfloat16_as_ushort(h2) | ((uint32_t)__bfloat16_as_ushort(h3)<<16);
                *(uint32_t*)(LoB + blkB + o1) = (uint32_t)__bfloat16_as_ushort(l2) | ((uint32_t)__bfloat16_as_ushort(l3)<<16);
            }
        }
    } else if (EPI == 6 || EPI == 7){
        #pragma unroll
        for (int mt=0; mt<4; mt++){
            float p0 = 0.f, p1 = 0.f;
            #pragma unroll
            for (int nt=0; nt<4; nt++){
                p0 += acc[mt][nt][0]*acc[mt][nt][0] + acc[mt][nt][1]*acc[mt][nt][1];
                p1 += acc[mt][nt][2]*acc[mt][nt][2] + acc[mt][nt][3]*acc[mt][nt][3];
            }
            p0 += __shfl_xor_sync(0xffffffffu, p0, 1);
            p0 += __shfl_xor_sync(0xffffffffu, p0, 2);
            p1 += __shfl_xor_sync(0xffffffffu, p1, 1);
            p1 += __shfl_xor_sync(0xffffffffu, p1, 2);
            if ((l&3) == 0){
                int r0 = wm*64 + mt*16 + (l>>2);
                s_red[r0][wn] = p0;
                s_red[r0+8][wn] = p1;
            }
        }
        __syncthreads();
        float Khv = HK[tnx];
        float sK = sqrtf(-Khv);
        if (wn == 0 && (l&3) == 0){
            #pragma unroll
            for (int mt=0; mt<4; mt++){
                #pragma unroll
                for (int hf=0; hf<2; hf++){
                    int r = wm*64 + mt*16 + (l>>2) + hf*8;
                    float n2 = s_red[r][0] + s_red[r][1] + s_red[r][2] + s_red[r][3];
                    float aa = sK*sqrtf(n2);
                    float sinc = (aa<1e-6f)?(1.f+aa*aa*(1.f/6.f)):(sinhf(aa)/fmaxf(aa,1e-12f));
                    float x0 = sqrtf(-1.f/Khv + sinc*sinc*n2);
                    int grow = tmy*256 + r;
                    int b = grow >> 11, sidx = grow & 2047;
                    size_t R = ((size_t)(b*Hh + tnx)<<11) + sidx;
                    AXout[R] = (EPI==6) ? (-GSCq*x0) : x0;
                    s_red[r][0] = (EPI==6) ? (GSCq*sinc) : sinc;
                }
            }
        }
        __syncthreads();
        char* HiB = (char*)OHi;
        char* LoB = (char*)OLo;
        #pragma unroll
        for (int mt=0; mt<4; mt++){
            int r0 = wm*64 + mt*16 + (l>>2);
            float sca = s_red[r0][0], scb = s_red[r0+8][0];
            int grow0 = tmy*256 + r0;
            int b = grow0 >> 11, sidx = grow0 & 2047;
            size_t R0 = ((size_t)(b*Hh + tnx)<<11) + sidx;
            uint32_t tr0 = (uint32_t)(R0>>7), rl0 = (uint32_t)(R0&127);
            uint32_t ro0 = rl0*128, ro1 = (rl0+8)*128;
            #pragma unroll
            for (int nt=0; nt<4; nt++){
                int col = wn*32 + nt*8 + (l&3)*2;
                float v0 = acc[mt][nt][0]*sca, v1 = acc[mt][nt][1]*sca;
                float v2 = acc[mt][nt][2]*scb, v3 = acc[mt][nt][3]*scb;
                int kcn = col>>6, g = (col>>3)&7, w2 = (col&7)*2;
                size_t blkB = (((size_t)tr0*2 + kcn)<<14);
                uint32_t o0 = SWZ(ro0 + g*16) + w2;
                uint32_t o1 = SWZ(ro1 + g*16) + w2;
                __nv_bfloat16 h0 = __float2bfloat16(v0), h1 = __float2bfloat16(v1);
                __nv_bfloat16 h2 = __float2bfloat16(v2), h3 = __float2bfloat16(v3);
                __nv_bfloat16 l0 = __float2bfloat16(v0 - __bfloat162float(h0));
                __nv_bfloat16 l1 = __float2bfloat16(v1 - __bfloat162float(h1));
                __nv_bfloat16 l2 = __float2bfloat16(v2 - __bfloat162float(h2));
                __nv_bfloat16 l3 = __float2bfloat16(v3 - __bfloat162float(h3));
                *(uint32_t*)(HiB + blkB + o0) = (uint32_t)__bfloat16_as_ushort(h0) | ((uint32_t)__bfloat16_as_ushort(h1)<<16);
                *(uint32_t*)(LoB + blkB + o0) = (uint32_t)__bfloat16_as_ushort(l0) | ((uint32_t)__bfloat16_as_ushort(l1)<<16);
                *(uint32_t*)(HiB + blkB + o1) = (uint32_t)__bfloat16_as_ushort(h2) | ((uint32_t)__bfloat16_as_ushort(h3)<<16);
                *(uint32_t*)(LoB + blkB + o1) = (uint32_t)__bfloat16_as_ushort(l2) | ((uint32_t)__bfloat16_as_ushort(l3)<<16);
            }
        }
    } else if (EPI == 8){
        char* HiB = (char*)OHi;
        char* LoB = (char*)OLo;
        #pragma unroll
        for (int mt=0; mt<4; mt++){
            int r0 = wm*64 + mt*16 + (l>>2);
            int grow0 = tmy*256 + r0;
            int b = grow0 >> 11;
            int s0 = grow0 & 2047, s1 = s0 + 8;
            size_t bh = (size_t)(b*Hh + tnx);
            size_t blk0 = (bh*(Sq/64) + (s0>>6)) << 14;
            size_t blk1 = (bh*(Sq/64) + (s1>>6)) << 14;
            uint32_t t0 = ((s0&63)>>3)*16 + (s0&7)*2;
            uint32_t t1 = ((s1&63)>>3)*16 + (s1&7)*2;
            #pragma unroll
            for (int nt=0; nt<4; nt++){
                int c0 = wn*32 + nt*8 + (l&3)*2, c1 = c0 + 1;
                float v0 = acc[mt][nt][0], v1 = acc[mt][nt][1];
                float v2 = acc[mt][nt][2], v3 = acc[mt][nt][3];
                __nv_bfloat16 h0 = __float2bfloat16(v0), h1 = __float2bfloat16(v1);
                __nv_bfloat16 h2 = __float2bfloat16(v2), h3 = __float2bfloat16(v3);
                __nv_bfloat16 l0 = __float2bfloat16(v0 - __bfloat162float(h0));
                __nv_bfloat16 l1 = __float2bfloat16(v1 - __bfloat162float(h1));
                __nv_bfloat16 l2 = __float2bfloat16(v2 - __bfloat162float(h2));
                __nv_bfloat16 l3 = __float2bfloat16(v3 - __bfloat162float(h3));
                uint32_t off00 = SWZ((uint32_t)(c0*128 + (t0 & 0x70))) + (t0 & 0xF);
                uint32_t off01 = SWZ((uint32_t)(c1*128 + (t0 & 0x70))) + (t0 & 0xF);
                uint32_t off10 = SWZ((uint32_t)(c0*128 + (t1 & 0x70))) + (t1 & 0xF);
                uint32_t off11 = SWZ((uint32_t)(c1*128 + (t1 & 0x70))) + (t1 & 0xF);
                *(unsigned short*)(HiB + blk0 + off00) = __bfloat16_as_ushort(h0);
                *(unsigned short*)(HiB + blk0 + off01) = __bfloat16_as_ushort(h1);
                *(unsigned short*)(HiB + blk1 + off10) = __bfloat16_as_ushort(h2);
                *(unsigned short*)(HiB + blk1 + off11) = __bfloat16_as_ushort(h3);
                *(unsigned short*)(LoB + blk0 + off00) = __bfloat16_as_ushort(l0);
                *(unsigned short*)(LoB + blk0 + off01) = __bfloat16_as_ushort(l1);
                *(unsigned short*)(LoB + blk1 + off10) = __bfloat16_as_ushort(l2);
                *(unsigned short*)(LoB + blk1 + off11) = __bfloat16_as_ushort(l3);
            }
        }
    } else {
        long long offC = (long long)bz*sC;
        float* Cb = C + offC + (size_t)tmy*256*ldc + (size_t)tnx*128;
        const float* Ab = (EPI==2) ? (ADD + offC + (size_t)tmy*256*ldc + (size_t)tnx*128) : nullptr;
        #pragma unroll
        for (int mt=0; mt<4; mt++){
            int r0 = wm*64 + mt*16 + (l>>2);
            #pragma unroll
            for (int nt=0; nt<4; nt++){
                int cc = wn*32 + nt*8 + (l&3)*2;
                float v0 = acc[mt][nt][0], v1 = acc[mt][nt][1];
                float v2 = acc[mt][nt][2], v3 = acc[mt][nt][3];
                if (EPI==2){
                    float2 x0 = *(const float2*)&Ab[(size_t)r0*ldc + cc];
                    float2 x1 = *(const float2*)&Ab[(size_t)(r0+8)*ldc + cc];
                    v0 += x0.x; v1 += x0.y; v2 += x1.x; v3 += x1.y;
                }
                *(float2*)&Cb[(size_t)r0*ldc + cc]     = make_float2(v0, v1);
                *(float2*)&Cb[(size_t)(r0+8)*ldc + cc] = make_float2(v2, v3);
            }
        }
    }
}

// ================= fused flash attention =================
#define FL_SMEM (196608 + 1024)

__global__ void __launch_bounds__(256, 1)
k_flash(const uint4* __restrict__ Qh, const uint4* __restrict__ Ql,
        const uint4* __restrict__ Kh, const uint4* __restrict__ Kl,
        const uint4* __restrict__ Vh, const uint4* __restrict__ Vl,
        const float* __restrict__ AX, const float* __restrict__ BX,
        uint4* __restrict__ OHi, uint4* __restrict__ OLo){
    extern __shared__ char dsm[];
    __shared__ __align__(8) unsigned long long s_mbar[5];
    __shared__ float s_ax[128], s_bx[128];
    int qt = 15 - blockIdx.x;
    int bh = blockIdx.y;
    int jmax = qt;
    uint32_t ab = (smem_u32(dsm) + 1023) & ~1023u;
    uint32_t qb = ab, kb = ab + 65536, vb = ab + 131072;
    int tid = threadIdx.x, wid = tid >> 5, l = tid & 31;

    uint32_t mQ, mKf, mKe, mVf, mVe;
    if (tid == 0){
        MB_INIT(smem_u32(&s_mbar[0]), 1);
        MB_INIT(smem_u32(&s_mbar[1]), 1);
        MB_INIT(smem_u32(&s_mbar[2]), 8);
        MB_INIT(smem_u32(&s_mbar[3]), 1);
        MB_INIT(smem_u32(&s_mbar[4]), 8);
    }
    mQ  = smem_u32(&s_mbar[0]); mKf = smem_u32(&s_mbar[1]); mKe = smem_u32(&s_mbar[2]);
    mVf = smem_u32(&s_mbar[3]); mVe = smem_u32(&s_mbar[4]);
    __syncthreads();

    if (tid < 128) s_ax[tid] = AX[(size_t)bh*Sq + qt*128 + tid];
    if (tid == 0){
        size_t qtr = (size_t)(bh*16 + qt)*2;
        MB_EXPECT_TX(mQ, 65536);
        BULK16K(qb,         (const void*)(Qh + qtr*1024), mQ);
        BULK16K(qb+16384,   (const void*)(Qh + (qtr+1)*1024), mQ);
        BULK16K(qb+32768,   (const void*)(Ql + qtr*1024), mQ);
        BULK16K(qb+49152,   (const void*)(Ql + (qtr+1)*1024), mQ);
        size_t ktr = (size_t)(bh*16)*2;
        MB_EXPECT_TX(mKf, 65536);
        BULK16K(kb,         (const void*)(Kh + ktr*1024), mKf);
        BULK16K(kb+16384,   (const void*)(Kh + (ktr+1)*1024), mKf);
        BULK16K(kb+32768,   (const void*)(Kl + ktr*1024), mKf);
        BULK16K(kb+49152,   (const void*)(Kl + (ktr+1)*1024), mKf);
        size_t vtr = (size_t)bh*(Sq/64);
        MB_EXPECT_TX(mVf, 65536);
        BULK16K(vb,         (const void*)(Vh + vtr*1024), mVf);
        BULK16K(vb+16384,   (const void*)(Vh + (vtr+1)*1024), mVf);
        BULK16K(vb+32768,   (const void*)(Vl + vtr*1024), mVf);
        BULK16K(vb+49152,   (const void*)(Vl + (vtr+1)*1024), mVf);
    }

    int l7 = l & 7;
    int rowadd = ((l>>4)&1)*8 + (l&7);
    int arow = (wid*16 + (l&7) + ((l>>3)&1)*8) * 128;
    int akg = (l>>4)&1, bkg = (l>>3)&1;
    int r0l = wid*16 + (l>>2);
    int colb = (l&3)*2;

    float o[16][4];
    #pragma unroll
    for (int i=0;i<16;i++){ o[i][0]=0.f; o[i][1]=0.f; o[i][2]=0.f; o[i][3]=0.f; }
    float m0 = -1e30f, m1 = -1e30f, ls0 = 0.f, ls1 = 0.f;

    MB_WAIT(mQ, 0);

    for (int j = 0; j <= jmax; j++){
        __syncthreads();
        if (tid < 128) s_bx[tid] = BX[(size_t)bh*Sq + j*128 + tid];
        __syncthreads();

        float s[16][4];
        #pragma unroll
        for (int i=0;i<16;i++){ s[i][0]=0.f; s[i][1]=0.f; s[i][2]=0.f; s[i][3]=0.f; }

        MB_WAIT(mKf, j&1);
        #pragma unroll
        for (int ch=0; ch<2; ch++){
            uint32_t qcH = qb + ch*16384, qcL = qb + 32768 + ch*16384;
            uint32_t kcH = kb + ch*16384, kcL = kb + 32768 + ch*16384;
            #pragma unroll
            for (int kk=0; kk<4; kk++){
                int kxA = ((kk*2 + akg) ^ l7) << 4;
                int kxB = ((kk*2 + bkg) ^ l7) << 4;
                uint32_t ahf[4], alf[4];
                LDSM4(ahf[0],ahf[1],ahf[2],ahf[3], qcH + arow + kxA);
                LDSM4(alf[0],alf[1],alf[2],alf[3], qcL + arow + kxA);
                #pragma unroll
                for (int tg=0; tg<4; tg++){
                    uint32_t bhf[4][2], blf[4][2];
                    #pragma unroll
                    for (int p=0; p<2; p++){
                        int br = (tg*32 + p*16 + rowadd)*128;
                        LDSM4(bhf[2*p][0],bhf[2*p][1],bhf[2*p+1][0],bhf[2*p+1][1], kcH + br + kxB);
                        LDSM4(blf[2*p][0],blf[2*p][1],blf[2*p+1][0],blf[2*p+1][1], kcL + br + kxB);
                    }
                    #pragma unroll
                    for (int q2=0; q2<4; q2++)
                        MMA16816(s[tg*4+q2], ahf, bhf[q2][0], bhf[q2][1]);
                    #pragma unroll
                    for (int q2=0; q2<4; q2++)
                        MMA16816(s[tg*4+q2], ahf, blf[q2][0], blf[q2][1]);
                    #pragma unroll
                    for (int q2=0; q2<4; q2++)
                        MMA16816(s[tg*4+q2], alf, bhf[q2][0], bhf[q2][1]);
                }
            }
        }
        if (l == 0) MB_ARRIVE(mKe);
        if (tid == 0 && j < jmax){
            MB_WAIT(mKe, j&1);
            size_t ktr = (size_t)(bh*16 + j + 1)*2;
            MB_EXPECT_TX(mKf, 65536);
            BULK16K(kb,       (const void*)(Kh + ktr*1024), mKf);
            BULK16K(kb+16384, (const void*)(Kh + (ktr+1)*1024), mKf);
            BULK16K(kb+32768, (const void*)(Kl + ktr*1024), mKf);
            BULK16K(kb+49152, (const void*)(Kl + (ktr+1)*1024), mKf);
        }

        float ax0 = s_ax[r0l], ax1 = s_ax[r0l + 8];
        bool diag = (j == qt);
        float mx0 = -1e30f, mx1 = -1e30f;
        #pragma unroll
        for (int nt=0; nt<16; nt++){
            int c0 = nt*8 + colb, c1 = c0 + 1;
            float b0 = s_bx[c0], b1 = s_bx[c1];
            s[nt][0] += ax0*b0; s[nt][1] += ax0*b1;
            s[nt][2] += ax1*b0; s[nt][3] += ax1*b1;
            if (diag){
                if (c0 > r0l)     s[nt][0] = -1e30f;
                if (c1 > r0l)     s[nt][1] = -1e30f;
                if (c0 > r0l + 8) s[nt][2] = -1e30f;
                if (c1 > r0l + 8) s[nt][3] = -1e30f;
            }
            mx0 = fmaxf(mx0, fmaxf(s[nt][0], s[nt][1]));
            mx1 = fmaxf(mx1, fmaxf(s[nt][2], s[nt][3]));
        }
        mx0 = fmaxf(mx0, __shfl_xor_sync(0xffffffffu, mx0, 1));
        mx0 = fmaxf(mx0, __shfl_xor_sync(0xffffffffu, mx0, 2));
        mx1 = fmaxf(mx1, __shfl_xor_sync(0xffffffffu, mx1, 1));
        mx1 = fmaxf(mx1, __shfl_xor_sync(0xffffffffu, mx1, 2));
        float mn0 = fmaxf(m0, mx0), mn1 = fmaxf(m1, mx1);
        float sc0 = __expf(m0 - mn0), sc1 = __expf(m1 - mn1);
        m0 = mn0; m1 = mn1;
        float su0 = 0.f, su1 = 0.f;
        #pragma unroll
        for (int nt=0; nt<16; nt++){
            s[nt][0] = (s[nt][0] > -1e29f) ? __expf(s[nt][0] - mn0) : 0.f;
            s[nt][1] = (s[nt][1] > -1e29f) ? __expf(s[nt][1] - mn0) : 0.f;
            s[nt][2] = (s[nt][2] > -1e29f) ? __expf(s[nt][2] - mn1) : 0.f;
            s[nt][3] = (s[nt][3] > -1e29f) ? __expf(s[nt][3] - mn1) : 0.f;
            su0 += s[nt][0] + s[nt][1];
            su1 += s[nt][2] + s[nt][3];
        }
        su0 += __shfl_xor_sync(0xffffffffu, su0, 1);
        su0 += __shfl_xor_sync(0xffffffffu, su0, 2);
        su1 += __shfl_xor_sync(0xffffffffu, su1, 1);
        su1 += __shfl_xor_sync(0xffffffffu, su1, 2);
        ls0 = ls0*sc0 + su0;
        ls1 = ls1*sc1 + su1;
        #pragma unroll
        for (int i=0;i<16;i++){ o[i][0]*=sc0; o[i][1]*=sc0; o[i][2]*=sc1; o[i][3]*=sc1; }

        uint32_t phi[16][2], plo[16][2];
        #pragma unroll
        for (int nt=0; nt<16; nt++){
            __nv_bfloat16 h0 = __float2bfloat16(s[nt][0]), h1 = __float2bfloat16(s[nt][1]);
            __nv_bfloat16 h2 = __float2bfloat16(s[nt][2]), h3 = __float2bfloat16(s[nt][3]);
            phi[nt][0] = (uint32_t)__bfloat16_as_ushort(h0) | ((uint32_t)__bfloat16_as_ushort(h1)<<16);
            phi[nt][1] = (uint32_t)__bfloat16_as_ushort(h2) | ((uint32_t)__bfloat16_as_ushort(h3)<<16);
            __nv_bfloat16 g0 = __float2bfloat16(s[nt][0]-__bfloat162float(h0));
            __nv_bfloat16 g1 = __float2bfloat16(s[nt][1]-__bfloat162float(h1));
            __nv_bfloat16 g2 = __float2bfloat16(s[nt][2]-__bfloat162float(h2));
            __nv_bfloat16 g3 = __float2bfloat16(s[nt][3]-__bfloat162float(h3));
            plo[nt][0] = (uint32_t)__bfloat16_as_ushort(g0) | ((uint32_t)__bfloat16_as_ushort(g1)<<16);
            plo[nt][1] = (uint32_t)__bfloat16_as_ushort(g2) | ((uint32_t)__bfloat16_as_ushort(g3)<<16);
        }

        MB_WAIT(mVf, j&1);
        #pragma unroll
        for (int kg=0; kg<8; kg++){
            uint32_t vbh = vb + (kg>>2)*16384, vbl = vb + 32768 + (kg>>2)*16384;
            int kxV = (((kg&3)*2 + bkg) ^ l7) << 4;
            uint32_t aPh[4] = { phi[2*kg][0], phi[2*kg][1], phi[2*kg+1][0], phi[2*kg+1][1] };
            uint32_t aPl[4] = { plo[2*kg][0], plo[2*kg][1], plo[2*kg+1][0], plo[2*kg+1][1] };
            #pragma unroll
            for (int dg=0; dg<4; dg++){
                uint32_t fh2[4][2], fl2[4][2];
                #pragma unroll
                for (int p=0; p<2; p++){
                    int br = (dg*32 + p*16 + rowadd)*128;
                    LDSM4(fh2[2*p][0],fh2[2*p][1],fh2[2*p+1][0],fh2[2*p+1][1], vbh + br + kxV);
                    LDSM4(fl2[2*p][0],fl2[2*p][1],fl2[2*p+1][0],fl2[2*p+1][1], vbl + br + kxV);
                }
                #pragma unroll
                for (int q2=0; q2<4; q2++)
                    MMA16816(o[dg*4+q2], aPh, fh2[q2][0], fh2[q2][1]);
                #pragma unroll
                for (int q2=0; q2<4; q2++)
                    MMA16816(o[dg*4+q2], aPh, fl2[q2][0], fl2[q2][1]);
                #pragma unroll
                for (int q2=0; q2<4; q2++)
                    MMA16816(o[dg*4+q2], aPl, fh2[q2][0], fh2[q2][1]);
            }
        }
        if (l == 0) MB_ARRIVE(mVe);
        if (tid == 0 && j < jmax){
            MB_WAIT(mVe, j&1);
            size_t vtr = (size_t)bh*(Sq/64) + (size_t)(j+1)*2;
            MB_EXPECT_TX(mVf, 65536);
            BULK16K(vb,       (const void*)(Vh + vtr*1024), mVf);
            BULK16K(vb+16384, (const void*)(Vh + (vtr+1)*1024), mVf);
            BULK16K(vb+32768, (const void*)(Vl + vtr*1024), mVf);
            BULK16K(vb+49152, (const void*)(Vl + (vtr+1)*1024), mVf);
        }
    }

    float inv0 = 1.f/ls0, inv1 = 1.f/ls1;
    int b = bh >> 4, h = bh & 15;
    int otr = b*16 + qt;
    int ocol0 = h*128;
    char* HiB = (char*)OHi;
    char* LoB = (char*)OLo;
    uint32_t ro0 = (uint32_t)(r0l*128), ro1 = (uint32_t)((r0l+8)*128);
    #pragma unroll
    for (int nt=0; nt<16; nt++){
        int col = ocol0 + nt*8 + colb;
        float v0 = o[nt][0]*inv0, v1 = o[nt][1]*inv0;
        float v2 = o[nt][2]*inv1, v3 = o[nt][3]*inv1;
        int kcn = col>>6, g = (col>>3)&7, w2 = (col&7)*2;
        size_t blkB = (((size_t)otr*(Dm/64) + kcn)<<14);
        uint32_t o0 = SWZ(ro0 + g*16) + w2;
        uint32_t o1 = SWZ(ro1 + g*16) + w2;
        __nv_bfloat16 h0 = __float2bfloat16(v0), h1 = __float2bfloat16(v1);
        __nv_bfloat16 h2 = __float2bfloat16(v2), h3 = __float2bfloat16(v3);
        __nv_bfloat16 l0 = __float2bfloat16(v0 - __bfloat162float(h0));
        __nv_bfloat16 l1 = __float2bfloat16(v1 - __bfloat162float(h1));
        __nv_bfloat16 l2 = __float2bfloat16(v2 - __bfloat162float(h2));
        __nv_bfloat16 l3 = __float2bfloat16(v3 - __bfloat162float(h3));
        *(uint32_t*)(HiB + blkB + o0) = (uint32_t)__bfloat16_as_ushort(h0) | ((uint32_t)__bfloat16_as_ushort(h1)<<16);
        *(uint32_t*)(LoB + blkB + o0) = (uint32_t)__bfloat16_as_ushort(l0) | ((uint32_t)__bfloat16_as_ushort(l1)<<16);
        *(uint32_t*)(HiB + blkB + o1) = (uint32_t)__bfloat16_as_ushort(h2) | ((uint32_t)__bfloat16_as_ushort(h3)<<16);
        *(uint32_t*)(LoB + blkB + o1) = (uint32_t)__bfloat16_as_ushort(l2) | ((uint32_t)__bfloat16_as_ushort(l3)<<16);
    }
}

// ================= launch =================
extern "C" void kernel_launch(void* const* d_in, const int* in_sizes, int n_in,
                              void* d_out, int out_size){
    const float* x      = (const float*)d_in[0];
    const float* scale1 = (const float*)d_in[2];
    const float* scale2 = (const float*)d_in[3];
    const float* Wq     = (const float*)d_in[4];
    const float* Wk     = (const float*)d_in[5];
    const float* Wv     = (const float*)d_in[6];
    const float* Wo     = (const float*)d_in[7];
    const float* headK  = (const float*)d_in[8];
    const float* W1     = (const float*)d_in[9];
    const float* W2     = (const float*)d_in[10];
    float* out = (float*)d_out;

    float *u,*ax,*bx;
    cudaGetSymbolAddress((void**)&u,    g_u);
    cudaGetSymbolAddress((void**)&ax,   g_ax);
    cudaGetSymbolAddress((void**)&bx,   g_bx);

    uint4 *vh,*vl,*ath,*atl,*fh,*fl,*qh,*ql_,*kh,*klo,*vth,*vtl;
    uint4 *wqh,*wql,*wkh,*wkl,*wvh,*wvl,*woh,*wol,*w1h,*w1l,*w2h,*w2l;
    cudaGetSymbolAddress((void**)&vh,  g_vh);   cudaGetSymbolAddress((void**)&vl,  g_vl);
    cudaGetSymbolAddress((void**)&ath, g_ath);  cudaGetSymbolAddress((void**)&atl, g_atl);
    cudaGetSymbolAddress((void**)&fh,  g_fh);   cudaGetSymbolAddress((void**)&fl,  g_fl);
    cudaGetSymbolAddress((void**)&qh,  g_qh);   cudaGetSymbolAddress((void**)&ql_, g_ql);
    cudaGetSymbolAddress((void**)&kh,  g_kh);   cudaGetSymbolAddress((void**)&klo, g_klo);
    cudaGetSymbolAddress((void**)&vth, g_vth);  cudaGetSymbolAddress((void**)&vtl, g_vtl);
    cudaGetSymbolAddress((void**)&wqh, g_WqTh); cudaGetSymbolAddress((void**)&wql, g_WqTl);
    cudaGetSymbolAddress((void**)&wkh, g_WkTh); cudaGetSymbolAddress((void**)&wkl, g_WkTl);
    cudaGetSymbolAddress((void**)&wvh, g_WvTh); cudaGetSymbolAddress((void**)&wvl, g_WvTl);
    cudaGetSymbolAddress((void**)&woh, g_WoTh); cudaGetSymbolAddress((void**)&wol, g_WoTl);
    cudaGetSymbolAddress((void**)&w1h, g_W1Th); cudaGetSymbolAddress((void**)&w1l, g_W1Tl);
    cudaGetSymbolAddress((void**)&w2h, g_W2Th); cudaGetSymbolAddress((void**)&w2l, g_W2Tl);

    cudaFuncSetAttribute(hmma_gemm<2>, cudaFuncAttributeMaxDynamicSharedMemorySize, HM_SMEM);
    cudaFuncSetAttribute(hmma_gemm<4>, cudaFuncAttributeMaxDynamicSharedMemorySize, HM_SMEM);
    cudaFuncSetAttribute(hmma_gemm<6>, cudaFuncAttributeMaxDynamicSharedMemorySize, HM_SMEM);
    cudaFuncSetAttribute(hmma_gemm<7>, cudaFuncAttributeMaxDynamicSharedMemorySize, HM_SMEM);
    cudaFuncSetAttribute(hmma_gemm<8>, cudaFuncAttributeMaxDynamicSharedMemorySize, HM_SMEM);
    cudaFuncSetAttribute(k_flash,      cudaFuncAttributeMaxDynamicSharedMemorySize, FL_SMEM);

    // side stream for weight splits (created per call; kernel_launch is invoked
    // only for correctness + capture, so the small host-side leak is bounded).
    cudaStream_t s2;
    cudaStreamCreateWithFlags(&s2, cudaStreamNonBlocking);
    cudaEvent_t evFork, evQKVsplit, evWsplit;
    cudaEventCreateWithFlags(&evFork,     cudaEventDisableTiming);
    cudaEventCreateWithFlags(&evQKVsplit, cudaEventDisableTiming);
    cudaEventCreateWithFlags(&evWsplit,   cudaEventDisableTiming);

    // fork: s2 branches from the main (legacy) stream
    cudaEventRecord(evFork, 0);
    cudaStreamWaitEvent(s2, evFork, 0);

    // s2: all weight splits (QKV splits first, then Wo/W1/W2)
    k_split_wT<<<dim3(Dm/128,  Dm/64  ),256,0,s2>>>(Wq, wqh, wql, Dm, Dm, Dm);
    k_split_wT<<<dim3(Dm/128,  Dm/64  ),256,0,s2>>>(Wk, wkh, wkl, Dm, Dm, Dm);
    k_split_wT<<<dim3(Dm/128,  Dm/64  ),256,0,s2>>>(Wv, wvh, wvl, Dm, Dm, Dm);
    cudaEventRecord(evQKVsplit, s2);
    k_split_wT<<<dim3(Dm/128,  Dm/64  ),256,0,s2>>>(Wo, woh, wol, Dm, Dm, Dm);
    k_split_wT<<<dim3(DFFd/128,Dm/64  ),256,0,s2>>>(W1, w1h, w1l, Dm, DFFd, DFFd);
    k_split_wT<<<dim3(Dm/128,  DFFd/64),256,0,s2>>>(W2, w2h, w2l, DFFd, Dm, Dm);
    cudaEventRecord(evWsplit, s2);

    // main: 1) u0 = log(x); v1 = norm1(u0) -> u fp32 + vh/vl TS (overlaps QKV splits)
    k_lognorm1<<<ROWS,256>>>(x, scale1, u, vh, vl);

    // main waits for Wq/Wk/Wv splits
    cudaStreamWaitEvent(0, evQKVsplit, 0);

    // 2) QKV projections with fused per-head epilogues
    dim3 gQ(Dm/128, ROWS/256);
    hmma_gemm<6><<<gQ,512,HM_SMEM>>>(vh, vl, wqh, wql, nullptr, nullptr, qh, ql_, ax, headK, Dm/64, 0, 2, ROWS/128, Dm/128, 0);
    hmma_gemm<7><<<gQ,512,HM_SMEM>>>(vh, vl, wkh, wkl, nullptr, nullptr, kh, klo, bx, headK, Dm/64, 0, 2, ROWS/128, Dm/128, 0);
    hmma_gemm<8><<<gQ,512,HM_SMEM>>>(vh, vl, wvh, wvl, nullptr, nullptr, vth, vtl, nullptr, nullptr, Dm/64, 0, 0, ROWS/128, Dm/128, 0);

    // 3) fused flash attention -> ath/atl TS (Wo/W1/W2 splits hide under this)
    k_flash<<<dim3(Sq/128, BHn),256,FL_SMEM>>>(qh, ql_, kh, klo, vth, vtl, ax, bx, ath, atl);

    // main waits for Wo/W1/W2 splits
    cudaStreamWaitEvent(0, evWsplit, 0);

    // 4) Wo projection + residual: u += attn@Wo
    hmma_gemm<2><<<gQ,512,HM_SMEM>>>(ath, atl, woh, wol, u, u, nullptr, nullptr, nullptr, nullptr, Dm/64, Dm, 0, ROWS/128, Dm/128, 0);

    // 5) v2 = norm2(u1) -> vh/vl TS
    k_norm2<<<ROWS,256>>>(u, scale2, vh, vl);

    // 6) FFN up + gelu (fast exact erf) -> fh/fl TS
    hmma_gemm<4><<<dim3(DFFd/128, ROWS/256),512,HM_SMEM>>>(
        vh, vl, w1h, w1l, nullptr, nullptr, fh, fl, nullptr, nullptr, Dm/64, 0, DFFd/64, ROWS/128, DFFd/128, 0);

    // 7) FFN down + residual: u += gelu@W2
    hmma_gemm<2><<<gQ,512,HM_SMEM>>>(fh, fl, w2h, w2l, u, u, nullptr, nullptr, nullptr, nullptr, DFFd/64, Dm, 0, ROWS/128, Dm/128, 0);

    // 8) out = exp_map(u2)
    k_expmap<<<ROWS,256>>>(u, out);
}

// round 16
// speedup vs baseline: 1.0255x; 1.0255x over previous
#include <cuda_runtime.h>
#include <cuda_bf16.h>
#include <math.h>
#include <stdint.h>

// Problem dims (fixed)
#define Bz   2
#define Sq   2048
#define Dm   2048
#define Hh   16
#define DHd  128
#define DFFd 8192
#define ROWS (Bz*Sq)       // 4096
#define BHn  (Bz*Hh)       // 32
#define EPSn 1e-6f

// ================= PTX helpers =================
__device__ __forceinline__ uint32_t smem_u32(const void* p){
    uint32_t r;
    asm("{ .reg .u64 t; cvta.to.shared.u64 t, %1; cvt.u32.u64 %0, t; }" : "=r"(r) : "l"(p));
    return r;
}
#define MB_INIT(addr,cnt) asm volatile("mbarrier.init.shared.b64 [%0], %1;"::"r"(addr),"r"(cnt):"memory")
#define MB_EXPECT_TX(addr,tx) asm volatile("mbarrier.arrive.expect_tx.shared.b64 _, [%0], %1;"::"r"(addr),"r"(tx):"memory")
#define MB_ARRIVE(addr) asm volatile("mbarrier.arrive.shared.b64 _, [%0];"::"r"(addr):"memory")
#define MB_WAIT(addr, ph) do { \
    asm volatile("{\n\t.reg .pred P1;\n\tWL%=:\n\t" \
        "mbarrier.try_wait.parity.acquire.cta.shared::cta.b64 P1, [%0], %1, 0x989680;\n\t" \
        "@P1 bra.uni WD%=;\n\tbra.uni WL%=;\n\tWD%=:\n\t}" \
        :: "r"(addr), "r"(ph) : "memory"); } while(0)
#define BULK16K(dst, src, mb) asm volatile( \
    "cp.async.bulk.shared::cta.global.mbarrier::complete_tx::bytes [%0], [%1], %2, [%3];" \
    :: "r"(dst), "l"(src), "r"(16384), "r"(mb) : "memory")
#define LDSM4(r0,r1,r2,r3,addr) asm volatile( \
    "ldmatrix.sync.aligned.m8n8.x4.shared.b16 {%0,%1,%2,%3},[%4];" \
    : "=r"(r0),"=r"(r1),"=r"(r2),"=r"(r3) : "r"(addr))
#define MMA16816(c, a, b0, b1) asm volatile( \
    "mma.sync.aligned.m16n8k16.row.col.f32.bf16.bf16.f32 " \
    "{%0,%1,%2,%3},{%4,%5,%6,%7},{%8,%9},{%0,%1,%2,%3};" \
    : "+f"((c)[0]),"+f"((c)[1]),"+f"((c)[2]),"+f"((c)[3]) \
    : "r"((a)[0]),"r"((a)[1]),"r"((a)[2]),"r"((a)[3]), "r"(b0),"r"(b1))
#define SWZ(o) ((o) ^ (((o)>>3)&0x70))

// fast exact-enough gelu: Abramowitz-Stegun 7.1.26 erf (|abs err|<=1.5e-7)
__device__ __forceinline__ float gelu_fast(float x){
    float z = fabsf(x) * 0.7071067811865475f;
    float t = __fdividef(1.f, fmaf(0.3275911f, z, 1.f));
    float p = fmaf(1.061405429f, t, -1.453152027f);
    p = fmaf(p, t, 1.421413741f);
    p = fmaf(p, t, -0.284496736f);
    p = fmaf(p, t, 0.254829592f);
    float e = p * t * __expf(-z*z);
    float er = 1.f - e;
    er = (x < 0.f) ? -er : er;
    return 0.5f * x * (1.f + er);
}

// ================= scratch (device globals) =================
__device__ float g_u   [(size_t)ROWS*Dm];
__device__ float g_ax  [(size_t)BHn*Sq];        // -gsc*x0_q
__device__ float g_bx  [(size_t)BHn*Sq];        // x0_k

// bf16 hi/lo tiled-swizzled (TS) operands, uint4 granules (= elems/8).
__device__ uint4 g_vh  [(size_t)ROWS*Dm/8],   g_vl  [(size_t)ROWS*Dm/8];
__device__ uint4 g_ath [(size_t)ROWS*Dm/8],   g_atl [(size_t)ROWS*Dm/8];
__device__ uint4 g_fh  [(size_t)ROWS*DFFd/8], g_fl  [(size_t)ROWS*DFFd/8];
__device__ uint4 g_qh  [(size_t)BHn*Sq*DHd/8], g_ql [(size_t)BHn*Sq*DHd/8];
__device__ uint4 g_kh  [(size_t)BHn*Sq*DHd/8], g_klo[(size_t)BHn*Sq*DHd/8];
__device__ uint4 g_vth [(size_t)BHn*DHd*Sq/8], g_vtl[(size_t)BHn*DHd*Sq/8];
__device__ uint4 g_WqTh[(size_t)Dm*Dm/8], g_WqTl[(size_t)Dm*Dm/8];
__device__ uint4 g_WkTh[(size_t)Dm*Dm/8], g_WkTl[(size_t)Dm*Dm/8];
__device__ uint4 g_WvTh[(size_t)Dm*Dm/8], g_WvTl[(size_t)Dm*Dm/8];
__device__ uint4 g_WoTh[(size_t)Dm*Dm/8], g_WoTl[(size_t)Dm*Dm/8];
__device__ uint4 g_W1Th[(size_t)Dm*DFFd/8], g_W1Tl[(size_t)Dm*DFFd/8];
__device__ uint4 g_W2Th[(size_t)Dm*DFFd/8], g_W2Tl[(size_t)Dm*DFFd/8];

union Pack8 { __nv_bfloat16 b[8]; uint4 v; };

// ================= reductions =================
__device__ __forceinline__ float warpSum(float v){
    #pragma unroll
    for (int o=16;o;o>>=1) v += __shfl_xor_sync(0xffffffffu, v, o);
    return v;
}
__device__ __forceinline__ float blockSum(float v){
    __shared__ float sh[32];
    int lane = threadIdx.x & 31, w = threadIdx.x >> 5, nw = (blockDim.x + 31) >> 5;
    v = warpSum(v);
    __syncthreads();
    if (lane == 0) sh[w] = v;
    __syncthreads();
    float r = (lane < nw) ? sh[lane] : 0.f;
    return warpSum(r);
}

__device__ __forceinline__ void split_pack(const float* xs, Pack8& H, Pack8& L){
    #pragma unroll
    for (int j=0;j<8;j++){
        __nv_bfloat16 h = __float2bfloat16(xs[j]);
        H.b[j] = h;
        L.b[j] = __float2bfloat16(xs[j] - __bfloat162float(h));
    }
}

// ================= fused elementwise kernels =================
// NOTE: x rows have stride 2049 floats (+1 offset) -> NOT 16B aligned; load scalars.
__global__ void k_lognorm1(const float* __restrict__ x, const float* __restrict__ scale,
                           float* __restrict__ u, uint4* __restrict__ vh, uint4* __restrict__ vl){
    int row = blockIdx.x, t = threadIdx.x;
    const float* xr = x + (size_t)row*(Dm+1) + 1 + t*8;
    float xs[8];
    #pragma unroll
    for (int j=0;j<8;j++) xs[j] = xr[j];
    float ss = 0.f;
    #pragma unroll
    for (int j=0;j<8;j++) ss += xs[j]*xs[j];
    float n2 = blockSum(ss);
    float a  = sqrtf(n2);
    float f  = (a < 1e-6f) ? (1.f - a*a*(1.f/6.f)) : (asinhf(a)/fmaxf(a,1e-12f));
    float rms = sqrtf(f*f*n2*(1.f/(float)Dm) + EPSn);
    float inv = 1.f/rms;
    float4 S0 = *(const float4*)(scale + t*8), S1 = *(const float4*)(scale + t*8 + 4);
    float sc[8] = {S0.x,S0.y,S0.z,S0.w,S1.x,S1.y,S1.z,S1.w};
    float us[8], vs[8];
    #pragma unroll
    for (int j=0;j<8;j++){ us[j] = f*xs[j]; vs[j] = sc[j]*us[j]*inv; }
    float* ur = u + (size_t)row*Dm + t*8;
    *(float4*)ur     = make_float4(us[0],us[1],us[2],us[3]);
    *(float4*)(ur+4) = make_float4(us[4],us[5],us[6],us[7]);
    Pack8 H, L; split_pack(vs, H, L);
    uint32_t tr = row>>7, rl = row&127;
    int kc = t>>3, gg = t&7;
    size_t blk = (((size_t)tr*(Dm/64) + kc)<<10) + (SWZ((uint32_t)(rl*128 + gg*16))>>4);
    vh[blk] = H.v; vl[blk] = L.v;
}

__global__ void k_norm2(const float* __restrict__ u, const float* __restrict__ scale,
                        uint4* __restrict__ vh, uint4* __restrict__ vl){
    int row = blockIdx.x, t = threadIdx.x;
    const float* ur = u + (size_t)row*Dm + t*8;
    float4 A = *(const float4*)ur, B = *(const float4*)(ur+4);
    float xs[8] = {A.x,A.y,A.z,A.w,B.x,B.y,B.z,B.w};
    float ss = 0.f;
    #pragma unroll
    for (int j=0;j<8;j++) ss += xs[j]*xs[j];
    float n2 = blockSum(ss);
    float rms = sqrtf(n2*(1.f/(float)Dm) + EPSn);
    float inv = 1.f/rms;
    float4 S0 = *(const float4*)(scale + t*8), S1 = *(const float4*)(scale + t*8 + 4);
    float sc[8] = {S0.x,S0.y,S0.z,S0.w,S1.x,S1.y,S1.z,S1.w};
    float vs[8];
    #pragma unroll
    for (int j=0;j<8;j++) vs[j] = sc[j]*xs[j]*inv;
    Pack8 H, L; split_pack(vs, H, L);
    uint32_t tr = row>>7, rl = row&127;
    int kc = t>>3, gg = t&7;
    size_t blk = (((size_t)tr*(Dm/64) + kc)<<10) + (SWZ((uint32_t)(rl*128 + gg*16))>>4);
    vh[blk] = H.v; vl[blk] = L.v;
}

__global__ void k_expmap(const float* __restrict__ u, float* __restrict__ out){
    int row = blockIdx.x, tid = threadIdx.x;
    const float* ur = u + (size_t)row*Dm;
    float loc[8]; float s = 0.f;
    #pragma unroll
    for (int j=0;j<8;j++){ float t = ur[tid + j*256]; loc[j]=t; s += t*t; }
    float n2 = blockSum(s);
    float a = sqrtf(n2);
    float sinc = (a < 1e-6f) ? (1.f + a*a*(1.f/6.f)) : (sinhf(a)/fmaxf(a,1e-12f));
    float x0 = sqrtf(1.f + sinc*sinc*n2);
    float* o = out + (size_t)row*(Dm+1);
    if (tid==0) o[0] = x0;
    #pragma unroll
    for (int j=0;j<8;j++){ int d = tid + j*256; o[1+d] = sinc*loc[j]; }
}

// ================= weight split =================
__global__ void k_split_wT(const float* __restrict__ W, uint4* __restrict__ Hi,
                           uint4* __restrict__ Lo, int K, int N, int ld){
    __shared__ float s[64][129];
    int tr = blockIdx.x, kc = blockIdx.y;
    int ntc = K >> 6;
    int n0 = tr*128, k0 = kc*64;
    int col = threadIdx.x & 127, r0 = threadIdx.x >> 7;
    #pragma unroll
    for (int i=0;i<32;i++){
        int r = r0 + i*2;
        s[r][col] = W[(size_t)(k0+r)*ld + n0 + col];
    }
    __syncthreads();
    size_t blk = ((size_t)tr*ntc + kc)*1024;
    #pragma unroll
    for (int i=0;i<4;i++){
        int gid = threadIdx.x + i*256;
        int nl = gid >> 3, g = gid & 7;
        Pack8 uh, ul;
        #pragma unroll
        for (int j=0;j<8;j++){
            float x = s[g*8+j][nl];
            __nv_bfloat16 h = __float2bfloat16(x);
            uh.b[j] = h;
            ul.b[j] = __float2bfloat16(x - __bfloat162float(h));
        }
        uint32_t off = SWZ((uint32_t)(nl*128 + g*16)) >> 4;
        Hi[blk + off] = uh.v;
        Lo[blk + off] = ul.v;
    }
}

// ================= HMMA bf16x3 pipelined GEMM: 256(M) x 128(N) tile, 512 thr =================
// EPI: 0 fp32 out; 2 fp32 += ADD; 3 TS out; 4 gelu + TS out; 6 Q-lorentz TS+ax;
//      7 K-lorentz TS+bx; 8 V-transpose TS.
#define STAGE_B 98304
#define HM_SMEM (2*STAGE_B + 1024)
#define GSCq 0.1767766952966369f

template<int EPI>
__global__ void __launch_bounds__(512, 1)
hmma_gemm(const uint4* __restrict__ Ah, const uint4* __restrict__ Al,
          const uint4* __restrict__ Bh, const uint4* __restrict__ Bl,
          float* __restrict__ C, const float* __restrict__ ADD,
          uint4* __restrict__ OHi, uint4* __restrict__ OLo,
          float* __restrict__ AXout, const float* __restrict__ HK,
          int nk, int ldc, int ntc, int mtb, int ntb, long long sC){
    extern __shared__ char dsm[];
    __shared__ __align__(8) unsigned long long s_mbar[4];
    __shared__ float s_red[256][4];
    int tnx = blockIdx.x, tmy = blockIdx.y, bz = blockIdx.z;
    int nkc = nk;
    int atr0 = bz*mtb + 2*tmy;
    int btr  = bz*ntb + tnx;

    uint32_t ab = (smem_u32(dsm) + 1023) & ~1023u;
    int tid = threadIdx.x, wid = tid >> 5, l = tid & 31;
    int wm = wid >> 2, wn = wid & 3;

    uint32_t mb[2], me[2];
    if (tid == 0){
        MB_INIT(smem_u32(&s_mbar[0]), 1);
        MB_INIT(smem_u32(&s_mbar[1]), 1);
        MB_INIT(smem_u32(&s_mbar[2]), 16);
        MB_INIT(smem_u32(&s_mbar[3]), 16);
    }
    mb[0] = smem_u32(&s_mbar[0]); mb[1] = smem_u32(&s_mbar[1]);
    me[0] = smem_u32(&s_mbar[2]); me[1] = smem_u32(&s_mbar[3]);
    __syncthreads();

    if (tid == 0){
        int pre = min(2, nkc);
        for (int c = 0; c < pre; c++){
            uint32_t base = ab + c*STAGE_B;
            MB_EXPECT_TX(mb[c], STAGE_B);
            BULK16K(base,         (const void*)(Ah + ((size_t)atr0*nk + c)*1024), mb[c]);
            BULK16K(base + 16384, (const void*)(Ah + ((size_t)(atr0+1)*nk + c)*1024), mb[c]);
            BULK16K(base + 32768, (const void*)(Al + ((size_t)atr0*nk + c)*1024), mb[c]);
            BULK16K(base + 49152, (const void*)(Al + ((size_t)(atr0+1)*nk + c)*1024), mb[c]);
            BULK16K(base + 65536, (const void*)(Bh + ((size_t)btr*nk + c)*1024), mb[c]);
            BULK16K(base + 81920, (const void*)(Bl + ((size_t)btr*nk + c)*1024), mb[c]);
        }
    }

    int arow[4], brow[2];
    #pragma unroll
    for (int mt=0; mt<4; mt++)
        arow[mt] = ((wm&1)*64 + mt*16 + (l&7) + ((l>>3)&1)*8) * 128;
    #pragma unroll
    for (int p=0; p<2; p++)
        brow[p] = (wn*32 + p*16 + ((l>>4)&1)*8 + (l&7)) * 128;
    int akg = (l>>4)&1, bkg = (l>>3)&1, l7 = l&7;
    uint32_t ablk = (uint32_t)(wm>>1)*16384u;

    float acc[4][4][4];
    #pragma unroll
    for (int i=0;i<4;i++)
        #pragma unroll
        for (int j=0;j<4;j++)
            #pragma unroll
            for (int t=0;t<4;t++) acc[i][j][t] = 0.f;

    for (int c = 0; c < nkc; c++){
        int s = c & 1;
        int ph = (c>>1)&1;
        MB_WAIT(mb[s], ph);
        uint32_t stg = ab + s*STAGE_B;
        uint32_t aHb = stg + ablk;
        uint32_t aLb = aHb + 32768;
        uint32_t bHb = stg + 65536, bLb = stg + 81920;
        #pragma unroll
        for (int kk = 0; kk < 4; kk++){
            int kxA = ((kk*2 + akg) ^ l7) << 4;
            int kxB = ((kk*2 + bkg) ^ l7) << 4;
            uint32_t bhr[4][2], blr[4][2];
            #pragma unroll
            for (int p=0; p<2; p++){
                LDSM4(bhr[2*p][0],bhr[2*p][1],bhr[2*p+1][0],bhr[2*p+1][1], bHb + brow[p] + kxB);
                LDSM4(blr[2*p][0],blr[2*p][1],blr[2*p+1][0],blr[2*p+1][1], bLb + brow[p] + kxB);
            }
            #pragma unroll
            for (int mt=0; mt<4; mt++){
                uint32_t ahf[4], alf[4];
                LDSM4(ahf[0],ahf[1],ahf[2],ahf[3], aHb + arow[mt] + kxA);
                LDSM4(alf[0],alf[1],alf[2],alf[3], aLb + arow[mt] + kxA);
                #pragma unroll
                for (int nt=0; nt<4; nt++)
                    MMA16816(acc[mt][nt], ahf, bhr[nt][0], bhr[nt][1]);
                #pragma unroll
                for (int nt=0; nt<4; nt++)
                    MMA16816(acc[mt][nt], ahf, blr[nt][0], blr[nt][1]);
                #pragma unroll
                for (int nt=0; nt<4; nt++)
                    MMA16816(acc[mt][nt], alf, bhr[nt][0], bhr[nt][1]);
            }
        }
        if (l == 0) MB_ARRIVE(me[s]);
        if (tid == 0 && c + 2 < nkc){
            MB_WAIT(me[s], ph);
            int cc = c + 2;
            uint32_t base = ab + s*STAGE_B;
            MB_EXPECT_TX(mb[s], STAGE_B);
            BULK16K(base,         (const void*)(Ah + ((size_t)atr0*nk + cc)*1024), mb[s]);
            BULK16K(base + 16384, (const void*)(Ah + ((size_t)(atr0+1)*nk + cc)*1024), mb[s]);
            BULK16K(base + 32768, (const void*)(Al + ((size_t)atr0*nk + cc)*1024), mb[s]);
            BULK16K(base + 49152, (const void*)(Al + ((size_t)(atr0+1)*nk + cc)*1024), mb[s]);
            BULK16K(base + 65536, (const void*)(Bh + ((size_t)btr*nk + cc)*1024), mb[s]);
            BULK16K(base + 81920, (const void*)(Bl + ((size_t)btr*nk + cc)*1024), mb[s]);
        }
    }

    // -------- epilogue --------
    if (EPI == 3 || EPI == 4){
        int otrBase = tmy*2, ocol0 = tnx*128;
        int otr = otrBase + (wm>>1);
        char* HiB = (char*)OHi;
        char* LoB = (char*)OLo;
        #pragma unroll
        for (int mt=0; mt<4; mt++){
            int rl = (wm&1)*64 + mt*16 + (l>>2);
            uint32_t ro0 = (uint32_t)(rl*128), ro1 = (uint32_t)((rl+8)*128);
            #pragma unroll
            for (int nt=0; nt<4; nt++){
                int col = ocol0 + wn*32 + nt*8 + (l&3)*2;
                float v0 = acc[mt][nt][0], v1 = acc[mt][nt][1];
                float v2 = acc[mt][nt][2], v3 = acc[mt][nt][3];
                if (EPI == 4){
                    v0 = gelu_fast(v0); v1 = gelu_fast(v1);
                    v2 = gelu_fast(v2); v3 = gelu_fast(v3);
                }
                int kcn = col>>6, g = (col>>3)&7, w2 = (col&7)*2;
                size_t blkB = (((size_t)otr*ntc + kcn)<<14);
                uint32_t o0 = SWZ(ro0 + g*16) + w2;
                uint32_t o1 = SWZ(ro1 + g*16) + w2;
                __nv_bfloat16 h0 = __float2bfloat16(v0), h1 = __float2bfloat16(v1);
                __nv_bfloat16 h2 = __float2bfloat16(v2), h3 = __float2bfloat16(v3);
                __nv_bfloat16 l0 = __float2bfloat16(v0 - __bfloat162float(h0));
                __nv_bfloat16 l1 = __float2bfloat16(v1 - __bfloat162float(h1));
                __nv_bfloat16 l2 = __float2bfloat16(v2 - __bfloat162float(h2));
                __nv_bfloat16 l3 = __float2bfloat16(v3 - __bfloat162float(h3));
                *(uint32_t*)(HiB + blkB + o0) = (uint32_t)__bfloat16_as_ushort(h0) | ((uint32_t)__bfloat16_as_ushort(h1)<<16);
                *(uint32_t*)(LoB + blkB + o0) = (uint32_t)__bfloat16_as_ushort(l0) | ((uint32_t)__bfloat16_as_ushort(l1)<<16);
                *(uint32_t*)(HiB + blkB + o1) = (uint32_t)__bfloat16_as_ushort(h2) | ((uint32_t)__bfloat16_as_ushort(h3)<<16);
                *(uint32_t*)(LoB + blkB + o1) = (uint32_t)__bfloat16_as_ushort(l2) | ((uint32_t)__bfloat16_as_ushort(l3)<<16);
            }
        }
    } else if (EPI == 6 || EPI == 7){
        #pragma unroll
        for (int mt=0; mt<4; mt++){
            float p0 = 0.f, p1 = 0.f;
            #pragma unroll
            for (int nt=0; nt<4; nt++){
                p0 += acc[mt][nt][0]*acc[mt][nt][0] + acc[mt][nt][1]*acc[mt][nt][1];
                p1 += acc[mt][nt][2]*acc[mt][nt][2] + acc[mt][nt][3]*acc[mt][nt][3];
            }
            p0 += __shfl_xor_sync(0xffffffffu, p0, 1);
            p0 += __shfl_xor_sync(0xffffffffu, p0, 2);
            p1 += __shfl_xor_sync(0xffffffffu, p1, 1);
            p1 += __shfl_xor_sync(0xffffffffu, p1, 2);
            if ((l&3) == 0){
                int r0 = wm*64 + mt*16 + (l>>2);
                s_red[r0][wn] = p0;
                s_red[r0+8][wn] = p1;
            }
        }
        __syncthreads();
        float Khv = HK[tnx];
        float sK = sqrtf(-Khv);
        if (wn == 0 && (l&3) == 0){
            #pragma unroll
            for (int mt=0; mt<4; mt++){
                #pragma unroll
                for (int hf=0; hf<2; hf++){
                    int r = wm*64 + mt*16 + (l>>2) + hf*8;
                    float n2 = s_red[r][0] + s_red[r][1] + s_red[r][2] + s_red[r][3];
                    float aa = sK*sqrtf(n2);
                    float sinc = (aa<1e-6f)?(1.f+aa*aa*(1.f/6.f)):(sinhf(aa)/fmaxf(aa,1e-12f));
                    float x0 = sqrtf(-1.f/Khv + sinc*sinc*n2);
                    int grow = tmy*256 + r;
                    int b = grow >> 11, sidx = grow & 2047;
                    size_t R = ((size_t)(b*Hh + tnx)<<11) + sidx;
                    AXout[R] = (EPI==6) ? (-GSCq*x0) : x0;
                    s_red[r][0] = (EPI==6) ? (GSCq*sinc) : sinc;
                }
            }
        }
        __syncthreads();
        char* HiB = (char*)OHi;
        char* LoB = (char*)OLo;
        #pragma unroll
        for (int mt=0; mt<4; mt++){
            int r0 = wm*64 + mt*16 + (l>>2);
            float sca = s_red[r0][0], scb = s_red[r0+8][0];
            int grow0 = tmy*256 + r0;
            int b = grow0 >> 11, sidx = grow0 & 2047;
            size_t R0 = ((size_t)(b*Hh + tnx)<<11) + sidx;
            uint32_t tr0 = (uint32_t)(R0>>7), rl0 = (uint32_t)(R0&127);
            uint32_t ro0 = rl0*128, ro1 = (rl0+8)*128;
            #pragma unroll
            for (int nt=0; nt<4; nt++){
                int col = wn*32 + nt*8 + (l&3)*2;
                float v0 = acc[mt][nt][0]*sca, v1 = acc[mt][nt][1]*sca;
                float v2 = acc[mt][nt][2]*scb, v3 = acc[mt][nt][3]*scb;
                int kcn = col>>6, g = (col>>3)&7, w2 = (col&7)*2;
                size_t blkB = (((size_t)tr0*2 + kcn)<<14);
                uint32_t o0 = SWZ(ro0 + g*16) + w2;
                uint32_t o1 = SWZ(ro1 + g*16) + w2;
                __nv_bfloat16 h0 = __float2bfloat16(v0), h1 = __float2bfloat16(v1);
                __nv_bfloat16 h2 = __float2bfloat16(v2), h3 = __float2bfloat16(v3);
                __nv_bfloat16 l0 = __float2bfloat16(v0 - __bfloat162float(h0));
                __nv_bfloat16 l1 = __float2bfloat16(v1 - __bfloat162float(h1));
                __nv_bfloat16 l2 = __float2bfloat16(v2 - __bfloat162float(h2));
                __nv_bfloat16 l3 = __float2bfloat16(v3 - __bfloat162float(h3));
                *(uint32_t*)(HiB + blkB + o0) = (uint32_t)__bfloat16_as_ushort(h0) | ((uint32_t)__bfloat16_as_ushort(h1)<<16);
                *(uint32_t*)(LoB + blkB + o0) = (uint32_t)__bfloat16_as_ushort(l0) | ((uint32_t)__bfloat16_as_ushort(l1)<<16);
                *(uint32_t*)(HiB + blkB + o1) = (uint32_t)__bfloat16_as_ushort(h2) | ((uint32_t)__bfloat16_as_ushort(h3)<<16);
                *(uint32_t*)(LoB + blkB + o1) = (uint32_t)__bfloat16_as_ushort(l2) | ((uint32_t)__bfloat16_as_ushort(l3)<<16);
            }
        }
    } else if (EPI == 8){
        char* HiB = (char*)OHi;
        char* LoB = (char*)OLo;
        #pragma unroll
        for (int mt=0; mt<4; mt++){
            int r0 = wm*64 + mt*16 + (l>>2);
            int grow0 = tmy*256 + r0;
            int b = grow0 >> 11;
            int s0 = grow0 & 2047, s1 = s0 + 8;
            size_t bh = (size_t)(b*Hh + tnx);
            size_t blk0 = (bh*(Sq/64) + (s0>>6)) << 14;
            size_t blk1 = (bh*(Sq/64) + (s1>>6)) << 14;
            uint32_t t0 = ((s0&63)>>3)*16 + (s0&7)*2;
            uint32_t t1 = ((s1&63)>>3)*16 + (s1&7)*2;
            #pragma unroll
            for (int nt=0; nt<4; nt++){
                int c0 = wn*32 + nt*8 + (l&3)*2, c1 = c0 + 1;
                float v0 = acc[mt][nt][0], v1 = acc[mt][nt][1];
                float v2 = acc[mt][nt][2], v3 = acc[mt][nt][3];
                __nv_bfloat16 h0 = __float2bfloat16(v0), h1 = __float2bfloat16(v1);
                __nv_bfloat16 h2 = __float2bfloat16(v2), h3 = __float2bfloat16(v3);
                __nv_bfloat16 l0 = __float2bfloat16(v0 - __bfloat162float(h0));
                __nv_bfloat16 l1 = __float2bfloat16(v1 - __bfloat162float(h1));
                __nv_bfloat16 l2 = __float2bfloat16(v2 - __bfloat162float(h2));
                __nv_bfloat16 l3 = __float2bfloat16(v3 - __bfloat162float(h3));
                uint32_t off00 = SWZ((uint32_t)(c0*128 + (t0 & 0x70))) + (t0 & 0xF);
                uint32_t off01 = SWZ((uint32_t)(c1*128 + (t0 & 0x70))) + (t0 & 0xF);
                uint32_t off10 = SWZ((uint32_t)(c0*128 + (t1 & 0x70))) + (t1 & 0xF);
                uint32_t off11 = SWZ((uint32_t)(c1*128 + (t1 & 0x70))) + (t1 & 0xF);
                *(unsigned short*)(HiB + blk0 + off00) = __bfloat16_as_ushort(h0);
                *(unsigned short*)(HiB + blk0 + off01) = __bfloat16_as_ushort(h1);
                *(unsigned short*)(HiB + blk1 + off10) = __bfloat16_as_ushort(h2);
                *(unsigned short*)(HiB + blk1 + off11) = __bfloat16_as_ushort(h3);
                *(unsigned short*)(LoB + blk0 + off00) = __bfloat16_as_ushort(l0);
                *(unsigned short*)(LoB + blk0 + off01) = __bfloat16_as_ushort(l1);
                *(unsigned short*)(LoB + blk1 + off10) = __bfloat16_as_ushort(l2);
                *(unsigned short*)(LoB + blk1 + off11) = __bfloat16_as_ushort(l3);
            }
        }
    } else {
        long long offC = (long long)bz*sC;
        float* Cb = C + offC + (size_t)tmy*256*ldc + (size_t)tnx*128;
        const float* Ab = (EPI==2) ? (ADD + offC + (size_t)tmy*256*ldc + (size_t)tnx*128) : nullptr;
        #pragma unroll
        for (int mt=0; mt<4; mt++){
            int r0 = wm*64 + mt*16 + (l>>2);
            #pragma unroll
            for (int nt=0; nt<4; nt++){
                int cc = wn*32 + nt*8 + (l&3)*2;
                float v0 = acc[mt][nt][0], v1 = acc[mt][nt][1];
                float v2 = acc[mt][nt][2], v3 = acc[mt][nt][3];
                if (EPI==2){
                    float2 x0 = *(const float2*)&Ab[(size_t)r0*ldc + cc];
                    float2 x1 = *(const float2*)&Ab[(size_t)(r0+8)*ldc + cc];
                    v0 += x0.x; v1 += x0.y; v2 += x1.x; v3 += x1.y;
                }
                *(float2*)&Cb[(size_t)r0*ldc + cc]     = make_float2(v0, v1);
                *(float2*)&Cb[(size_t)(r0+8)*ldc + cc] = make_float2(v2, v3);
            }
        }
    }
}

// ================= fused flash attention =================
#define FL_SMEM (196608 + 1024)

__global__ void __launch_bounds__(256, 1)
k_flash(const uint4* __restrict__ Qh, const uint4* __restrict__ Ql,
        const uint4* __restrict__ Kh, const uint4* __restrict__ Kl,
        const uint4* __restrict__ Vh, const uint4* __restrict__ Vl,
        const float* __restrict__ AX, const float* __restrict__ BX,
        uint4* __restrict__ OHi, uint4* __restrict__ OLo){
    extern __shared__ char dsm[];
    __shared__ __align__(8) unsigned long long s_mbar[5];
    __shared__ float s_ax[128], s_bx[128];
    int qt = 15 - blockIdx.x;
    int bh = blockIdx.y;
    int jmax = qt;
    uint32_t ab = (smem_u32(dsm) + 1023) & ~1023u;
    uint32_t qb = ab, kb = ab + 65536, vb = ab + 131072;
    int tid = threadIdx.x, wid = tid >> 5, l = tid & 31;

    uint32_t mQ, mKf, mKe, mVf, mVe;
    if (tid == 0){
        MB_INIT(smem_u32(&s_mbar[0]), 1);
        MB_INIT(smem_u32(&s_mbar[1]), 1);
        MB_INIT(smem_u32(&s_mbar[2]), 8);
        MB_INIT(smem_u32(&s_mbar[3]), 1);
        MB_INIT(smem_u32(&s_mbar[4]), 8);
    }
    mQ  = smem_u32(&s_mbar[0]); mKf = smem_u32(&s_mbar[1]); mKe = smem_u32(&s_mbar[2]);
    mVf = smem_u32(&s_mbar[3]); mVe = smem_u32(&s_mbar[4]);
    __syncthreads();

    if (tid < 128) s_ax[tid] = AX[(size_t)bh*Sq + qt*128 + tid];
    if (tid == 0){
        size_t qtr = (size_t)(bh*16 + qt)*2;
        MB_EXPECT_TX(mQ, 65536);
        BULK16K(qb,         (const void*)(Qh + qtr*1024), mQ);
        BULK16K(qb+16384,   (const void*)(Qh + (qtr+1)*1024), mQ);
        BULK16K(qb+32768,   (const void*)(Ql + qtr*1024), mQ);
        BULK16K(qb+49152,   (const void*)(Ql + (qtr+1)*1024), mQ);
        size_t ktr = (size_t)(bh*16)*2;
        MB_EXPECT_TX(mKf, 65536);
        BULK16K(kb,         (const void*)(Kh + ktr*1024), mKf);
        BULK16K(kb+16384,   (const void*)(Kh + (ktr+1)*1024), mKf);
        BULK16K(kb+32768,   (const void*)(Kl + ktr*1024), mKf);
        BULK16K(kb+49152,   (const void*)(Kl + (ktr+1)*1024), mKf);
        size_t vtr = (size_t)bh*(Sq/64);
        MB_EXPECT_TX(mVf, 65536);
        BULK16K(vb,         (const void*)(Vh + vtr*1024), mVf);
        BULK16K(vb+16384,   (const void*)(Vh + (vtr+1)*1024), mVf);
        BULK16K(vb+32768,   (const void*)(Vl + vtr*1024), mVf);
        BULK16K(vb+49152,   (const void*)(Vl + (vtr+1)*1024), mVf);
    }

    int l7 = l & 7;
    int rowadd = ((l>>4)&1)*8 + (l&7);
    int arow = (wid*16 + (l&7) + ((l>>3)&1)*8) * 128;
    int akg = (l>>4)&1, bkg = (l>>3)&1;
    int r0l = wid*16 + (l>>2);
    int colb = (l&3)*2;

    float o[16][4];
    #pragma unroll
    for (int i=0;i<16;i++){ o[i][0]=0.f; o[i][1]=0.f; o[i][2]=0.f; o[i][3]=0.f; }
    float m0 = -1e30f, m1 = -1e30f, ls0 = 0.f, ls1 = 0.f;

    MB_WAIT(mQ, 0);

    for (int j = 0; j <= jmax; j++){
        __syncthreads();
        if (tid < 128) s_bx[tid] = BX[(size_t)bh*Sq + j*128 + tid];
        __syncthreads();

        float s[16][4];
        #pragma unroll
        for (int i=0;i<16;i++){ s[i][0]=0.f; s[i][1]=0.f; s[i][2]=0.f; s[i][3]=0.f; }

        MB_WAIT(mKf, j&1);
        #pragma unroll
        for (int ch=0; ch<2; ch++){
            uint32_t qcH = qb + ch*16384, qcL = qb + 32768 + ch*16384;
            uint32_t kcH = kb + ch*16384, kcL = kb + 32768 + ch*16384;
            #pragma unroll
            for (int kk=0; kk<4; kk++){
                int kxA = ((kk*2 + akg) ^ l7) << 4;
                int kxB = ((kk*2 + bkg) ^ l7) << 4;
                uint32_t ahf[4], alf[4];
                LDSM4(ahf[0],ahf[1],ahf[2],ahf[3], qcH + arow + kxA);
                LDSM4(alf[0],alf[1],alf[2],alf[3], qcL + arow + kxA);
                #pragma unroll
                for (int tg=0; tg<4; tg++){
                    uint32_t bhf[4][2], blf[4][2];
                    #pragma unroll
                    for (int p=0; p<2; p++){
                        int br = (tg*32 + p*16 + rowadd)*128;
                        LDSM4(bhf[2*p][0],bhf[2*p][1],bhf[2*p+1][0],bhf[2*p+1][1], kcH + br + kxB);
                        LDSM4(blf[2*p][0],blf[2*p][1],blf[2*p+1][0],blf[2*p+1][1], kcL + br + kxB);
                    }
                    #pragma unroll
                    for (int q2=0; q2<4; q2++)
                        MMA16816(s[tg*4+q2], ahf, bhf[q2][0], bhf[q2][1]);
                    #pragma unroll
                    for (int q2=0; q2<4; q2++)
                        MMA16816(s[tg*4+q2], ahf, blf[q2][0], blf[q2][1]);
                    #pragma unroll
                    for (int q2=0; q2<4; q2++)
                        MMA16816(s[tg*4+q2], alf, bhf[q2][0], bhf[q2][1]);
                }
            }
        }
        if (l == 0) MB_ARRIVE(mKe);
        if (tid == 0 && j < jmax){
            MB_WAIT(mKe, j&1);
            size_t ktr = (size_t)(bh*16 + j + 1)*2;
            MB_EXPECT_TX(mKf, 65536);
            BULK16K(kb,       (const void*)(Kh + ktr*1024), mKf);
            BULK16K(kb+16384, (const void*)(Kh + (ktr+1)*1024), mKf);
            BULK16K(kb+32768, (const void*)(Kl + ktr*1024), mKf);
            BULK16K(kb+49152, (const void*)(Kl + (ktr+1)*1024), mKf);
        }

        float ax0 = s_ax[r0l], ax1 = s_ax[r0l + 8];
        bool diag = (j == qt);
        float mx0 = -1e30f, mx1 = -1e30f;
        #pragma unroll
        for (int nt=0; nt<16; nt++){
            int c0 = nt*8 + colb, c1 = c0 + 1;
            float b0 = s_bx[c0], b1 = s_bx[c1];
            s[nt][0] += ax0*b0; s[nt][1] += ax0*b1;
            s[nt][2] += ax1*b0; s[nt][3] += ax1*b1;
            if (diag){
                if (c0 > r0l)     s[nt][0] = -1e30f;
                if (c1 > r0l)     s[nt][1] = -1e30f;
                if (c0 > r0l + 8) s[nt][2] = -1e30f;
                if (c1 > r0l + 8) s[nt][3] = -1e30f;
            }
            mx0 = fmaxf(mx0, fmaxf(s[nt][0], s[nt][1]));
            mx1 = fmaxf(mx1, fmaxf(s[nt][2], s[nt][3]));
        }
        mx0 = fmaxf(mx0, __shfl_xor_sync(0xffffffffu, mx0, 1));
        mx0 = fmaxf(mx0, __shfl_xor_sync(0xffffffffu, mx0, 2));
        mx1 = fmaxf(mx1, __shfl_xor_sync(0xffffffffu, mx1, 1));
        mx1 = fmaxf(mx1, __shfl_xor_sync(0xffffffffu, mx1, 2));
        float mn0 = fmaxf(m0, mx0), mn1 = fmaxf(m1, mx1);
        float sc0 = __expf(m0 - mn0), sc1 = __expf(m1 - mn1);
        m0 = mn0; m1 = mn1;
        float su0 = 0.f, su1 = 0.f;
        #pragma unroll
        for (int nt=0; nt<16; nt++){
            s[nt][0] = (s[nt][0] > -1e29f) ? __expf(s[nt][0] - mn0) : 0.f;
            s[nt][1] = (s[nt][1] > -1e29f) ? __expf(s[nt][1] - mn0) : 0.f;
            s[nt][2] = (s[nt][2] > -1e29f) ? __expf(s[nt][2] - mn1) : 0.f;
            s[nt][3] = (s[nt][3] > -1e29f) ? __expf(s[nt][3] - mn1) : 0.f;
            su0 += s[nt][0] + s[nt][1];
            su1 += s[nt][2] + s[nt][3];
        }
        su0 += __shfl_xor_sync(0xffffffffu, su0, 1);
        su0 += __shfl_xor_sync(0xffffffffu, su0, 2);
        su1 += __shfl_xor_sync(0xffffffffu, su1, 1);
        su1 += __shfl_xor_sync(0xffffffffu, su1, 2);
        ls0 = ls0*sc0 + su0;
        ls1 = ls1*sc1 + su1;
        #pragma unroll
        for (int i=0;i<16;i++){ o[i][0]*=sc0; o[i][1]*=sc0; o[i][2]*=sc1; o[i][3]*=sc1; }

        uint32_t phi[16][2], plo[16][2];
        #pragma unroll
        for (int nt=0; nt<16; nt++){
            __nv_bfloat16 h0 = __float2bfloat16(s[nt][0]), h1 = __float2bfloat16(s[nt][1]);
            __nv_bfloat16 h2 = __float2bfloat16(s[nt][2]), h3 = __float2bfloat16(s[nt][3]);
            phi[nt][0] = (uint32_t)__bfloat16_as_ushort(h0) | ((uint32_t)__bfloat16_as_ushort(h1)<<16);
            phi[nt][1] = (uint32_t)__bfloat16_as_ushort(h2) | ((uint32_t)__bfloat16_as_ushort(h3)<<16);
            __nv_bfloat16 g0 = __float2bfloat16(s[nt][0]-__bfloat162float(h0));
            __nv_bfloat16 g1 = __float2bfloat16(s[nt][1]-__bfloat162float(h1));
            __nv_bfloat16 g2 = __float2bfloat16(s[nt][2]-__bfloat162float(h2));
            __nv_bfloat16 g3 = __float2bfloat16(s[nt][3]-__bfloat162float(h3));
            plo[nt][0] = (uint32_t)__bfloat16_as_ushort(g0) | ((uint32_t)__bfloat16_as_ushort(g1)<<16);
            plo[nt][1] = (uint32_t)__bfloat16_as_ushort(g2) | ((uint32_t)__bfloat16_as_ushort(g3)<<16);
        }

        MB_WAIT(mVf, j&1);
        #pragma unroll
        for (int kg=0; kg<8; kg++){
            uint32_t vbh = vb + (kg>>2)*16384, vbl = vb + 32768 + (kg>>2)*16384;
            int kxV = (((kg&3)*2 + bkg) ^ l7) << 4;
            uint32_t aPh[4] = { phi[2*kg][0], phi[2*kg][1], phi[2*kg+1][0], phi[2*kg+1][1] };
            uint32_t aPl[4] = { plo[2*kg][0], plo[2*kg][1], plo[2*kg+1][0], plo[2*kg+1][1] };
            #pragma unroll
            for (int dg=0; dg<4; dg++){
                uint32_t fh2[4][2], fl2[4][2];
                #pragma unroll
                for (int p=0; p<2; p++){
                    int br = (dg*32 + p*16 + rowadd)*128;
                    LDSM4(fh2[2*p][0],fh2[2*p][1],fh2[2*p+1][0],fh2[2*p+1][1], vbh + br + kxV);
                    LDSM4(fl2[2*p][0],fl2[2*p][1],fl2[2*p+1][0],fl2[2*p+1][1], vbl + br + kxV);
                }
                #pragma unroll
                for (int q2=0; q2<4; q2++)
                    MMA16816(o[dg*4+q2], aPh, fh2[q2][0], fh2[q2][1]);
                #pragma unroll
                for (int q2=0; q2<4; q2++)
                    MMA16816(o[dg*4+q2], aPh, fl2[q2][0], fl2[q2][1]);
                #pragma unroll
                for (int q2=0; q2<4; q2++)
                    MMA16816(o[dg*4+q2], aPl, fh2[q2][0], fh2[q2][1]);
            }
        }
        if (l == 0) MB_ARRIVE(mVe);
        if (tid == 0 && j < jmax){
            MB_WAIT(mVe, j&1);
            size_t vtr = (size_t)bh*(Sq/64) + (size_t)(j+1)*2;
            MB_EXPECT_TX(mVf, 65536);
            BULK16K(vb,       (const void*)(Vh + vtr*1024), mVf);
            BULK16K(vb+16384, (const void*)(Vh + (vtr+1)*1024), mVf);
            BULK16K(vb+32768, (const void*)(Vl + vtr*1024), mVf);
            BULK16K(vb+49152, (const void*)(Vl + (vtr+1)*1024), mVf);
        }
    }

    float inv0 = 1.f/ls0, inv1 = 1.f/ls1;
    int b = bh >> 4, h = bh & 15;
    int otr = b*16 + qt;
    int ocol0 = h*128;
    char* HiB = (char*)OHi;
    char* LoB = (char*)OLo;
    uint32_t ro0 = (uint32_t)(r0l*128), ro1 = (uint32_t)((r0l+8)*128);
    #pragma unroll
    for (int nt=0; nt<16; nt++){
        int col = ocol0 + nt*8 + colb;
        float v0 = o[nt][0]*inv0, v1 = o[nt][1]*inv0;
        float v2 = o[nt][2]*inv1, v3 = o[nt][3]*inv1;
        int kcn = col>>6, g = (col>>3)&7, w2 = (col&7)*2;
        size_t blkB = (((size_t)otr*(Dm/64) + kcn)<<14);
        uint32_t o0 = SWZ(ro0 + g*16) + w2;
        uint32_t o1 = SWZ(ro1 + g*16) + w2;
        __nv_bfloat16 h0 = __float2bfloat16(v0), h1 = __float2bfloat16(v1);
        __nv_bfloat16 h2 = __float2bfloat16(v2), h3 = __float2bfloat16(v3);
        __nv_bfloat16 l0 = __float2bfloat16(v0 - __bfloat162float(h0));
        __nv_bfloat16 l1 = __float2bfloat16(v1 - __bfloat162float(h1));
        __nv_bfloat16 l2 = __float2bfloat16(v2 - __bfloat162float(h2));
        __nv_bfloat16 l3 = __float2bfloat16(v3 - __bfloat162float(h3));
        *(uint32_t*)(HiB + blkB + o0) = (uint32_t)__bfloat16_as_ushort(h0) | ((uint32_t)__bfloat16_as_ushort(h1)<<16);
        *(uint32_t*)(LoB + blkB + o0) = (uint32_t)__bfloat16_as_ushort(l0) | ((uint32_t)__bfloat16_as_ushort(l1)<<16);
        *(uint32_t*)(HiB + blkB + o1) = (uint32_t)__bfloat16_as_ushort(h2) | ((uint32_t)__bfloat16_as_ushort(h3)<<16);
        *(uint32_t*)(LoB + blkB + o1) = (uint32_t)__bfloat16_as_ushort(l2) | ((uint32_t)__bfloat16_as_ushort(l3)<<16);
    }
}

// ================= launch =================
extern "C" void kernel_launch(void* const* d_in, const int* in_sizes, int n_in,
                              void* d_out, int out_size){
    const float* x      = (const float*)d_in[0];
    const float* scale1 = (const float*)d_in[2];
    const float* scale2 = (const float*)d_in[3];
    const float* Wq     = (const float*)d_in[4];
    const float* Wk     = (const float*)d_in[5];
    const float* Wv     = (const float*)d_in[6];
    const float* Wo     = (const float*)d_in[7];
    const float* headK  = (const float*)d_in[8];
    const float* W1     = (const float*)d_in[9];
    const float* W2     = (const float*)d_in[10];
    float* out = (float*)d_out;

    float *u,*ax,*bx;
    cudaGetSymbolAddress((void**)&u,    g_u);
    cudaGetSymbolAddress((void**)&ax,   g_ax);
    cudaGetSymbolAddress((void**)&bx,   g_bx);

    uint4 *vh,*vl,*ath,*atl,*fh,*fl,*qh,*ql_,*kh,*klo,*vth,*vtl;
    uint4 *wqh,*wql,*wkh,*wkl,*wvh,*wvl,*woh,*wol,*w1h,*w1l,*w2h,*w2l;
    cudaGetSymbolAddress((void**)&vh,  g_vh);   cudaGetSymbolAddress((void**)&vl,  g_vl);
    cudaGetSymbolAddress((void**)&ath, g_ath);  cudaGetSymbolAddress((void**)&atl, g_atl);
    cudaGetSymbolAddress((void**)&fh,  g_fh);   cudaGetSymbolAddress((void**)&fl,  g_fl);
    cudaGetSymbolAddress((void**)&qh,  g_qh);   cudaGetSymbolAddress((void**)&ql_, g_ql);
    cudaGetSymbolAddress((void**)&kh,  g_kh);   cudaGetSymbolAddress((void**)&klo, g_klo);
    cudaGetSymbolAddress((void**)&vth, g_vth);  cudaGetSymbolAddress((void**)&vtl, g_vtl);
    cudaGetSymbolAddress((void**)&wqh, g_WqTh); cudaGetSymbolAddress((void**)&wql, g_WqTl);
    cudaGetSymbolAddress((void**)&wkh, g_WkTh); cudaGetSymbolAddress((void**)&wkl, g_WkTl);
    cudaGetSymbolAddress((void**)&wvh, g_WvTh); cudaGetSymbolAddress((void**)&wvl, g_WvTl);
    cudaGetSymbolAddress((void**)&woh, g_WoTh); cudaGetSymbolAddress((void**)&wol, g_WoTl);
    cudaGetSymbolAddress((void**)&w1h, g_W1Th); cudaGetSymbolAddress((void**)&w1l, g_W1Tl);
    cudaGetSymbolAddress((void**)&w2h, g_W2Th); cudaGetSymbolAddress((void**)&w2l, g_W2Tl);

    cudaFuncSetAttribute(hmma_gemm<2>, cudaFuncAttributeMaxDynamicSharedMemorySize, HM_SMEM);
    cudaFuncSetAttribute(hmma_gemm<4>, cudaFuncAttributeMaxDynamicSharedMemorySize, HM_SMEM);
    cudaFuncSetAttribute(hmma_gemm<6>, cudaFuncAttributeMaxDynamicSharedMemorySize, HM_SMEM);
    cudaFuncSetAttribute(hmma_gemm<7>, cudaFuncAttributeMaxDynamicSharedMemorySize, HM_SMEM);
    cudaFuncSetAttribute(hmma_gemm<8>, cudaFuncAttributeMaxDynamicSharedMemorySize, HM_SMEM);
    cudaFuncSetAttribute(k_flash,      cudaFuncAttributeMaxDynamicSharedMemorySize, FL_SMEM);

    // side stream for weight splits (created per call; kernel_launch is invoked
    // only for correctness + capture, so the small host-side leak is bounded).
    cudaStream_t s2;
    cudaStreamCreateWithFlags(&s2, cudaStreamNonBlocking);
    cudaEvent_t evFork, evQKVsplit, evWsplit;
    cudaEventCreateWithFlags(&evFork,     cudaEventDisableTiming);
    cudaEventCreateWithFlags(&evQKVsplit, cudaEventDisableTiming);
    cudaEventCreateWithFlags(&evWsplit,   cudaEventDisableTiming);

    // fork: s2 branches from the main (legacy) stream
    cudaEventRecord(evFork, 0);
    cudaStreamWaitEvent(s2, evFork, 0);

    // s2: all weight splits (QKV splits first, then Wo/W1/W2)
    k_split_wT<<<dim3(Dm/128,  Dm/64  ),256,0,s2>>>(Wq, wqh, wql, Dm, Dm, Dm);
    k_split_wT<<<dim3(Dm/128,  Dm/64  ),256,0,s2>>>(Wk, wkh, wkl, Dm, Dm, Dm);
    k_split_wT<<<dim3(Dm/128,  Dm/64  ),256,0,s2>>>(Wv, wvh, wvl, Dm, Dm, Dm);
    cudaEventRecord(evQKVsplit, s2);
    k_split_wT<<<dim3(Dm/128,  Dm/64  ),256,0,s2>>>(Wo, woh, wol, Dm, Dm, Dm);
    k_split_wT<<<dim3(DFFd/128,Dm/64  ),256,0,s2>>>(W1, w1h, w1l, Dm, DFFd, DFFd);
    k_split_wT<<<dim3(Dm/128,  DFFd/64),256,0,s2>>>(W2, w2h, w2l, DFFd, Dm, Dm);
    cudaEventRecord(evWsplit, s2);

    // main: 1) u0 = log(x); v1 = norm1(u0) -> u fp32 + vh/vl TS (overlaps QKV splits)
    k_lognorm1<<<ROWS,256>>>(x, scale1, u, vh, vl);

    // main waits for Wq/Wk/Wv splits
    cudaStreamWaitEvent(0, evQKVsplit, 0);

    // 2) QKV projections with fused per-head epilogues
    dim3 gQ(Dm/128, ROWS/256);
    hmma_gemm<6><<<gQ,512,HM_SMEM>>>(vh, vl, wqh, wql, nullptr, nullptr, qh, ql_, ax, headK, Dm/64, 0, 2, ROWS/128, Dm/128, 0);
    hmma_gemm<7><<<gQ,512,HM_SMEM>>>(vh, vl, wkh, wkl, nullptr, nullptr, kh, klo, bx, headK, Dm/64, 0, 2, ROWS/128, Dm/128, 0);
    hmma_gemm<8><<<gQ,512,HM_SMEM>>>(vh, vl, wvh, wvl, nullptr, nullptr, vth, vtl, nullptr, nullptr, Dm/64, 0, 0, ROWS/128, Dm/128, 0);

    // 3) fused flash attention -> ath/atl TS (Wo/W1/W2 splits hide under this)
    k_flash<<<dim3(Sq/128, BHn),256,FL_SMEM>>>(qh, ql_, kh, klo, vth, vtl, ax, bx, ath, atl);

    // main waits for Wo/W1/W2 splits
    cudaStreamWaitEvent(0, evWsplit, 0);

    // 4) Wo projection + residual: u += attn@Wo
    hmma_gemm<2><<<gQ,512,HM_SMEM>>>(ath, atl, woh, wol, u, u, nullptr, nullptr, nullptr, nullptr, Dm/64, Dm, 0, ROWS/128, Dm/128, 0);

    // 5) v2 = norm2(u1) -> vh/vl TS
    k_norm2<<<ROWS,256>>>(u, scale2, vh, vl);

    // 6) FFN up + gelu (fast exact erf) -> fh/fl TS
    hmma_gemm<4><<<dim3(DFFd/128, ROWS/256),512,HM_SMEM>>>(
        vh, vl, w1h, w1l, nullptr, nullptr, fh, fl, nullptr, nullptr, Dm/64, 0, DFFd/64, ROWS/128, DFFd/128, 0);

    // 7) FFN down + residual: u += gelu@W2
    hmma_gemm<2><<<gQ,512,HM_SMEM>>>(fh, fl, w2h, w2l, u, u, nullptr, nullptr, nullptr, nullptr, DFFd/64, Dm, 0, ROWS/128, Dm/128, 0);

    // 8) out = exp_map(u2)
    k_expmap<<<ROWS,256>>>(u, out);
}